// round 1
// baseline (speedup 1.0000x reference)
#include <cuda_runtime.h>
#include <cuda_bf16.h>
#include <math.h>

// Problem constants
#define BATCH 2
#define SEQ 2048
#define DIM 1024
#define NHEAD 16
#define HDIM 64
#define QKV_COLS (3 * DIM)          // 3072
#define ROWS (BATCH * SEQ)          // 4096
#define SCALE 0.03125f              // 1024^-0.5

// Scratch in device globals (no allocation allowed)
__device__ float g_qkv[ROWS * QKV_COLS];     // [4096, 3072]
__device__ float g_att[ROWS * DIM];          // [4096, 1024]  (b, s, h*64+d)

// ---------------------------------------------------------------------------
// Generic tiled GEMM with bias: C[M,N] = A[M,K] @ W[K,N] + bias[N]
// 64x64 tile, BK=16, 256 threads, 4x4 microtile per thread.
// ---------------------------------------------------------------------------
__global__ __launch_bounds__(256) void gemm_bias_kernel(
    const float* __restrict__ A, const float* __restrict__ W,
    const float* __restrict__ bias, float* __restrict__ C,
    int M, int N, int K)
{
    __shared__ float As[64][17];   // [row][k]
    __shared__ float Bs[16][65];   // [k][col]

    const int t  = threadIdx.x;
    const int tx = t & 15;         // 0..15
    const int ty = t >> 4;         // 0..15
    const int row0 = blockIdx.y * 64;
    const int col0 = blockIdx.x * 64;

    float acc[4][4];
#pragma unroll
    for (int i = 0; i < 4; i++)
#pragma unroll
        for (int j = 0; j < 4; j++) acc[i][j] = 0.0f;

    const int ar = t >> 2;          // 0..63
    const int ac = (t & 3) * 4;     // 0,4,8,12
    const int br = t >> 4;          // 0..15
    const int bc = (t & 15) * 4;    // 0..60

    for (int k0 = 0; k0 < K; k0 += 16) {
        // Load A tile 64x16 (one float4 per thread)
        float4 av = *reinterpret_cast<const float4*>(
            A + (size_t)(row0 + ar) * K + k0 + ac);
        As[ar][ac + 0] = av.x; As[ar][ac + 1] = av.y;
        As[ar][ac + 2] = av.z; As[ar][ac + 3] = av.w;
        // Load B tile 16x64 (one float4 per thread)
        float4 bv = *reinterpret_cast<const float4*>(
            W + (size_t)(k0 + br) * N + col0 + bc);
        Bs[br][bc + 0] = bv.x; Bs[br][bc + 1] = bv.y;
        Bs[br][bc + 2] = bv.z; Bs[br][bc + 3] = bv.w;
        __syncthreads();

#pragma unroll
        for (int kk = 0; kk < 16; kk++) {
            float a[4], b[4];
#pragma unroll
            for (int i = 0; i < 4; i++) a[i] = As[ty * 4 + i][kk];
#pragma unroll
            for (int j = 0; j < 4; j++) b[j] = Bs[kk][tx * 4 + j];
#pragma unroll
            for (int i = 0; i < 4; i++)
#pragma unroll
                for (int j = 0; j < 4; j++)
                    acc[i][j] = fmaf(a[i], b[j], acc[i][j]);
        }
        __syncthreads();
    }

#pragma unroll
    for (int i = 0; i < 4; i++) {
        const int r = row0 + ty * 4 + i;
#pragma unroll
        for (int j = 0; j < 4; j++) {
            const int c = col0 + tx * 4 + j;
            C[(size_t)r * N + c] = acc[i][j] + bias[c];
        }
    }
}

// ---------------------------------------------------------------------------
// Flash-attention (fp32). grid = (S/64, B*H). block = 256.
// qkv layout: row (b*S+s), col h*192 + {q:0..63, k:64..127, v:128..191}
// Output: g_att[(b*S+s)*DIM + h*64 + d]
// ---------------------------------------------------------------------------
struct AttnSmem {
    float Qs[64][65];
    float Ks[64][65];
    float Vs[64][65];
    float Ps[64][65];
    float m[64];
    float l[64];
    float alpha[64];
    float red[64][4];
};

__global__ __launch_bounds__(256) void attn_kernel(
    const float* __restrict__ qkv, float* __restrict__ out)
{
    extern __shared__ char smem_raw[];
    AttnSmem& sm = *reinterpret_cast<AttnSmem*>(smem_raw);

    const int t  = threadIdx.x;
    const int tx = t & 15;
    const int ty = t >> 4;
    const int qt = blockIdx.x;        // query tile 0..31
    const int bh = blockIdx.y;        // 0..31
    const int b  = bh >> 4;
    const int h  = bh & 15;

    const size_t base = (size_t)b * SEQ * QKV_COLS + (size_t)h * (3 * HDIM);
    const int q0 = qt * 64;

    // Load Q tile (pre-scaled)
    for (int idx = t; idx < 64 * 64; idx += 256) {
        const int r = idx >> 6, c = idx & 63;
        sm.Qs[r][c] = SCALE * qkv[base + (size_t)(q0 + r) * QKV_COLS + c];
    }
    if (t < 64) { sm.m[t] = -INFINITY; sm.l[t] = 0.0f; }

    float o[4][4];
#pragma unroll
    for (int i = 0; i < 4; i++)
#pragma unroll
        for (int j = 0; j < 4; j++) o[i][j] = 0.0f;

    const int r4 = ty * 4;
    const int c4 = tx * 4;
    const int srow = t >> 2;        // softmax row handled by this thread
    const int sseg = t & 3;         // 16-col segment
    const int sc0  = sseg * 16;

    for (int kt = 0; kt < SEQ / 64; kt++) {
        __syncthreads();   // protect Ks/Vs/Qs from previous iteration readers
        const int k0 = kt * 64;
        for (int idx = t; idx < 64 * 64; idx += 256) {
            const int r = idx >> 6, c = idx & 63;
            const size_t rowoff = base + (size_t)(k0 + r) * QKV_COLS;
            sm.Ks[r][c] = qkv[rowoff + 64 + c];
            sm.Vs[r][c] = qkv[rowoff + 128 + c];
        }
        __syncthreads();

        // Phase A: S = Q @ K^T (already scaled)
        float s[4][4];
#pragma unroll
        for (int i = 0; i < 4; i++)
#pragma unroll
            for (int j = 0; j < 4; j++) s[i][j] = 0.0f;
#pragma unroll 8
        for (int kk = 0; kk < 64; kk++) {
            float a[4], bb[4];
#pragma unroll
            for (int i = 0; i < 4; i++) a[i]  = sm.Qs[r4 + i][kk];
#pragma unroll
            for (int j = 0; j < 4; j++) bb[j] = sm.Ks[c4 + j][kk];
#pragma unroll
            for (int i = 0; i < 4; i++)
#pragma unroll
                for (int j = 0; j < 4; j++)
                    s[i][j] = fmaf(a[i], bb[j], s[i][j]);
        }
#pragma unroll
        for (int i = 0; i < 4; i++)
#pragma unroll
            for (int j = 0; j < 4; j++) sm.Ps[r4 + i][c4 + j] = s[i][j];
        __syncthreads();

        // Phase B: online softmax. Each thread: one row, one 16-col segment.
        float lmax = -INFINITY;
#pragma unroll
        for (int c = 0; c < 16; c++) lmax = fmaxf(lmax, sm.Ps[srow][sc0 + c]);
        sm.red[srow][sseg] = lmax;
        __syncthreads();
        if (t < 64) {
            const float mo = sm.m[t];
            float mn = fmaxf(fmaxf(sm.red[t][0], sm.red[t][1]),
                             fmaxf(sm.red[t][2], sm.red[t][3]));
            mn = fmaxf(mn, mo);
            sm.alpha[t] = __expf(mo - mn);
            sm.m[t] = mn;
        }
        __syncthreads();
        const float mn = sm.m[srow];
        float lsum = 0.0f;
#pragma unroll
        for (int c = 0; c < 16; c++) {
            const float p = __expf(sm.Ps[srow][sc0 + c] - mn);
            sm.Ps[srow][sc0 + c] = p;
            lsum += p;
        }
        sm.red[srow][sseg] = lsum;
        __syncthreads();
        if (t < 64) {
            sm.l[t] = sm.l[t] * sm.alpha[t] +
                      (sm.red[t][0] + sm.red[t][1] + sm.red[t][2] + sm.red[t][3]);
        }

        // Rescale running O by alpha (alpha already synced above)
        float ai[4];
#pragma unroll
        for (int i = 0; i < 4; i++) ai[i] = sm.alpha[r4 + i];
#pragma unroll
        for (int i = 0; i < 4; i++)
#pragma unroll
            for (int j = 0; j < 4; j++) o[i][j] *= ai[i];

        // Phase C: O += P @ V
#pragma unroll 8
        for (int kk = 0; kk < 64; kk++) {
            float p[4], v[4];
#pragma unroll
            for (int i = 0; i < 4; i++) p[i] = sm.Ps[r4 + i][kk];
#pragma unroll
            for (int j = 0; j < 4; j++) v[j] = sm.Vs[kk][c4 + j];
#pragma unroll
            for (int i = 0; i < 4; i++)
#pragma unroll
                for (int j = 0; j < 4; j++)
                    o[i][j] = fmaf(p[i], v[j], o[i][j]);
        }
    }

    __syncthreads();   // l[] writes visible to all
    float inv_l[4];
#pragma unroll
    for (int i = 0; i < 4; i++) inv_l[i] = 1.0f / sm.l[r4 + i];

#pragma unroll
    for (int i = 0; i < 4; i++) {
        const int srow_g = q0 + r4 + i;
        float* orow = out + ((size_t)b * SEQ + srow_g) * DIM + h * HDIM;
#pragma unroll
        for (int j = 0; j < 4; j++)
            orow[c4 + j] = o[i][j] * inv_l[i];
    }
}

// ---------------------------------------------------------------------------
extern "C" void kernel_launch(void* const* d_in, const int* in_sizes, int n_in,
                              void* d_out, int out_size)
{
    const float* x      = (const float*)d_in[0];
    const float* w_qkv  = (const float*)d_in[1];
    const float* b_qkv  = (const float*)d_in[2];
    const float* w_proj = (const float*)d_in[3];
    const float* b_proj = (const float*)d_in[4];
    float* out = (float*)d_out;

    float *qkv, *att;
    cudaGetSymbolAddress((void**)&qkv, g_qkv);
    cudaGetSymbolAddress((void**)&att, g_att);

    cudaFuncSetAttribute(attn_kernel, cudaFuncAttributeMaxDynamicSharedMemorySize,
                         (int)sizeof(AttnSmem));

    // 1) QKV projection: [4096,1024] @ [1024,3072] + b
    gemm_bias_kernel<<<dim3(QKV_COLS / 64, ROWS / 64), 256>>>(
        x, w_qkv, b_qkv, qkv, ROWS, QKV_COLS, DIM);

    // 2) Multi-head attention
    attn_kernel<<<dim3(SEQ / 64, BATCH * NHEAD), 256, sizeof(AttnSmem)>>>(qkv, att);

    // 3) Output projection: [4096,1024] @ [1024,1024] + b
    gemm_bias_kernel<<<dim3(DIM / 64, ROWS / 64), 256>>>(
        att, w_proj, b_proj, out, ROWS, DIM, DIM);
}

// round 3
// speedup vs baseline: 2.9449x; 2.9449x over previous
#include <cuda_runtime.h>
#include <cuda_bf16.h>
#include <math.h>
#include <stdint.h>

// Problem constants
#define BATCH 2
#define SEQ 2048
#define DIM 1024
#define NHEAD 16
#define HDIM 64
#define QKV_COLS (3 * DIM)          // 3072
#define ROWS (BATCH * SEQ)          // 4096
#define SCALE 0.03125f              // 1024^-0.5

// Scratch in device globals (no allocation allowed)
__device__ float g_qkv[ROWS * QKV_COLS];       // [4096, 3072]
__device__ float g_att[ROWS * DIM];            // [4096, 1024]
__device__ float g_wqkvT[QKV_COLS * DIM];      // [3072, 1024]
__device__ float g_wprojT[DIM * DIM];          // [1024, 1024]

// ---------------------------------------------------------------------------
// mma.sync helpers (base sm_103-safe; no tcgen05)
// ---------------------------------------------------------------------------
__device__ __forceinline__ uint32_t f2tf32(float f) {
    uint32_t r;
    asm("cvt.rna.tf32.f32 %0, %1;" : "=r"(r) : "f"(f));
    return r;
}

__device__ __forceinline__ void mma_tf32(float c[4],
    uint32_t a0, uint32_t a1, uint32_t a2, uint32_t a3,
    uint32_t b0, uint32_t b1)
{
    asm volatile(
        "mma.sync.aligned.m16n8k8.row.col.f32.tf32.tf32.f32 "
        "{%0,%1,%2,%3}, {%4,%5,%6,%7}, {%8,%9}, {%0,%1,%2,%3};"
        : "+f"(c[0]), "+f"(c[1]), "+f"(c[2]), "+f"(c[3])
        : "r"(a0), "r"(a1), "r"(a2), "r"(a3), "r"(b0), "r"(b1));
}

__device__ __forceinline__ uint32_t smem_u32(const void* p) {
    uint32_t a;
    asm("{ .reg .u64 t; cvta.to.shared.u64 t, %1; cvt.u32.u64 %0, t; }"
        : "=r"(a) : "l"(p));
    return a;
}

__device__ __forceinline__ void cp_async16(uint32_t dst, const void* src) {
    asm volatile("cp.async.cg.shared.global [%0], [%1], 16;"
                 :: "r"(dst), "l"(src));
}
#define CP_COMMIT() asm volatile("cp.async.commit_group;" ::: "memory")
#define CP_WAIT0()  asm volatile("cp.async.wait_group 0;" ::: "memory")
#define CP_WAIT1()  asm volatile("cp.async.wait_group 1;" ::: "memory")

// ---------------------------------------------------------------------------
// Transpose: out[n*K + k] = in[k*N + n]. block (32,8), grid (N/32, K/32).
// ---------------------------------------------------------------------------
__global__ __launch_bounds__(256) void transpose_kernel(
    const float* __restrict__ in, float* __restrict__ out, int K, int N)
{
    __shared__ float tile[32][33];
    const int n0 = blockIdx.x * 32;
    const int k0 = blockIdx.y * 32;
    const int tx = threadIdx.x, ty = threadIdx.y;
#pragma unroll
    for (int i = 0; i < 32; i += 8)
        tile[ty + i][tx] = in[(size_t)(k0 + ty + i) * N + n0 + tx];
    __syncthreads();
#pragma unroll
    for (int i = 0; i < 32; i += 8)
        out[(size_t)(n0 + ty + i) * K + k0 + tx] = tile[tx][ty + i];
}

// ---------------------------------------------------------------------------
// mma.sync tf32 GEMM: C[M,N] = A[M,K] @ Bt[N,K]^T + bias[N]
// 128x128 tile, BK=32, cp.async double-buffered, 256 threads (8 warps).
// Warp tile: 64 rows x 32 cols (warp grid 2x4).
// ---------------------------------------------------------------------------
#define BK 32
#define GPAD 36                         // row stride (floats) for A/B tiles
#define GSTG (128 * GPAD)               // floats per stage
#define GEMM_SMEM_BYTES (4 * GSTG * 4)  // 2 stages A + 2 stages B = 73728 B

__global__ __launch_bounds__(256) void gemm_mma_kernel(
    const float* __restrict__ A, const float* __restrict__ Bt,
    const float* __restrict__ bias, float* __restrict__ C,
    int M, int N, int K)
{
    extern __shared__ float dsm[];
    float* sA = dsm;                 // [2][128][GPAD]
    float* sB = dsm + 2 * GSTG;      // [2][128][GPAD]
    const uint32_t sAb = smem_u32(sA);
    const uint32_t sBb = smem_u32(sB);

    const int t    = threadIdx.x;
    const int lane = t & 31;
    const int w    = t >> 5;
    const int wm   = w >> 2;         // 0..1  -> 64-row slab
    const int wn   = w & 3;          // 0..3  -> 32-col slab
    const int g    = lane >> 2;      // 0..7
    const int t4   = lane & 3;       // 0..3
    const int row0 = blockIdx.y * 128;
    const int col0 = blockIdx.x * 128;

    // load indices: 256 threads x 4 float4 per tile (128 rows x 8 float4)
    const int lrow = t >> 1;              // 0..127
    const int lc4  = (t & 1) * 4;         // 0 or 4 (float4 index)

    float acc[4][4][4];
#pragma unroll
    for (int i = 0; i < 4; i++)
#pragma unroll
        for (int j = 0; j < 4; j++)
#pragma unroll
            for (int q = 0; q < 4; q++) acc[i][j][q] = 0.0f;

    const int nchunk = K / BK;

    // ---- stage loader (cp.async) ----
    auto load_stage = [&](int stg, int ck) {
        const int k0 = ck * BK;
#pragma unroll
        for (int i = 0; i < 2; i++) {
            const int r = lrow;                    // 0..127
            const int c4 = lc4 + i * 8;            // 0,4 / 8,12 -> but BK=32 => 8 float4/row
            // c4 in {0,4} + i*? -> need florat4 cols 0..7; use (t&1)*4 + i? 
            (void)c4;
        }
        // simpler: 4 iterations of 256 threads over 1024 float4 per tile
#pragma unroll
        for (int i = 0; i < 4; i++) {
            const int id = t + i * 256;            // 0..1023
            const int r  = id >> 3;                // 0..127
            const int c  = id & 7;                 // float4 col
            cp_async16(sAb + (uint32_t)((stg * GSTG + r * GPAD + c * 4) * 4),
                       A + (size_t)(row0 + r) * K + k0 + c * 4);
            cp_async16(sBb + (uint32_t)((stg * GSTG + r * GPAD + c * 4) * 4),
                       Bt + (size_t)(col0 + r) * K + k0 + c * 4);
        }
    };

    load_stage(0, 0);
    CP_COMMIT();

    for (int ck = 0; ck < nchunk; ck++) {
        if (ck + 1 < nchunk) {
            load_stage((ck + 1) & 1, ck + 1);
            CP_COMMIT();
            CP_WAIT1();
        } else {
            CP_WAIT0();
        }
        __syncthreads();

        const float* cA = sA + (ck & 1) * GSTG;
        const float* cB = sB + (ck & 1) * GSTG;

#pragma unroll
        for (int ks = 0; ks < 4; ks++) {
            const int k0 = ks * 8;
            uint32_t af[4][4];
#pragma unroll
            for (int mb = 0; mb < 4; mb++) {
                const int r = wm * 64 + mb * 16 + g;
                af[mb][0] = f2tf32(cA[r * GPAD + k0 + t4]);
                af[mb][1] = f2tf32(cA[(r + 8) * GPAD + k0 + t4]);
                af[mb][2] = f2tf32(cA[r * GPAD + k0 + t4 + 4]);
                af[mb][3] = f2tf32(cA[(r + 8) * GPAD + k0 + t4 + 4]);
            }
            uint32_t bf[4][2];
#pragma unroll
            for (int nb = 0; nb < 4; nb++) {
                const int c = wn * 32 + nb * 8 + g;
                bf[nb][0] = f2tf32(cB[c * GPAD + k0 + t4]);
                bf[nb][1] = f2tf32(cB[c * GPAD + k0 + t4 + 4]);
            }
#pragma unroll
            for (int mb = 0; mb < 4; mb++)
#pragma unroll
                for (int nb = 0; nb < 4; nb++)
                    mma_tf32(acc[mb][nb], af[mb][0], af[mb][1], af[mb][2],
                             af[mb][3], bf[nb][0], bf[nb][1]);
        }
        __syncthreads();
    }

    // Epilogue: write C + bias
#pragma unroll
    for (int mb = 0; mb < 4; mb++) {
        const int r = row0 + wm * 64 + mb * 16 + g;
#pragma unroll
        for (int nb = 0; nb < 4; nb++) {
            const int c = col0 + wn * 32 + nb * 8 + 2 * t4;
            const float b0 = bias[c], b1 = bias[c + 1];
            float2 v0 = make_float2(acc[mb][nb][0] + b0, acc[mb][nb][1] + b1);
            float2 v1 = make_float2(acc[mb][nb][2] + b0, acc[mb][nb][3] + b1);
            *reinterpret_cast<float2*>(C + (size_t)r * N + c) = v0;
            *reinterpret_cast<float2*>(C + (size_t)(r + 8) * N + c) = v1;
        }
    }
}

// ---------------------------------------------------------------------------
// Flash-attention with mma.sync tf32.
// grid = (S/64, B*H), block = 256 (8 warps; warp grid 4x2).
// ---------------------------------------------------------------------------
#define QPAD 68   // stride for Qs/Ks/Ps (mod 32 == 4 -> conflict-free frags)
#define VPAD 72   // stride for Vs (mod 32 == 8)

struct AttnSmem {
    float Qs[64][QPAD];
    float Ks[64][QPAD];
    float Ps[64][QPAD];
    float Vs[64][VPAD];
    float m[64];
    float l[64];
    float alpha[64];
    float red[64][4];
};

__global__ __launch_bounds__(256) void attn_kernel(
    const float* __restrict__ qkv, float* __restrict__ out)
{
    extern __shared__ char smem_raw[];
    AttnSmem& sm = *reinterpret_cast<AttnSmem*>(smem_raw);

    const int t    = threadIdx.x;
    const int lane = t & 31;
    const int w    = t >> 5;
    const int wm   = w >> 1;          // 0..3  -> 16-row slab
    const int wn   = w & 1;           // 0..1  -> 32-col slab
    const int g    = lane >> 2;
    const int t4   = lane & 3;
    const int qr   = wm * 16;         // warp's S/P/O row base
    const int nc   = wn * 32;         // warp's col base (keys or dims)

    const int qt = blockIdx.x;
    const int bh = blockIdx.y;
    const int b  = bh >> 4;
    const int h  = bh & 15;

    const size_t base = (size_t)b * SEQ * QKV_COLS + (size_t)h * (3 * HDIM);
    const int q0 = qt * 64;

    // Load Q tile (pre-scaled)
    for (int idx = t; idx < 64 * 64; idx += 256) {
        const int r = idx >> 6, c = idx & 63;
        sm.Qs[r][c] = SCALE * qkv[base + (size_t)(q0 + r) * QKV_COLS + c];
    }
    if (t < 64) { sm.m[t] = -INFINITY; sm.l[t] = 0.0f; }

    float obuf[4][4];  // O fragments: 4 n-blocks of m16n8
#pragma unroll
    for (int i = 0; i < 4; i++)
#pragma unroll
        for (int j = 0; j < 4; j++) obuf[i][j] = 0.0f;

    const int srow = t >> 2;        // softmax row for this thread
    const int sseg = t & 3;         // 16-col segment
    const int sc0  = sseg * 16;

    for (int kt = 0; kt < SEQ / 64; kt++) {
        __syncthreads();
        const int k0g = kt * 64;
        for (int idx = t; idx < 64 * 64; idx += 256) {
            const int r = idx >> 6, c = idx & 63;
            const size_t rowoff = base + (size_t)(k0g + r) * QKV_COLS;
            sm.Ks[r][c] = qkv[rowoff + 64 + c];
            sm.Vs[r][c] = qkv[rowoff + 128 + c];
        }
        __syncthreads();

        // ---- S = Q @ K^T via mma.sync (k = 64) ----
        float sacc[4][4];
#pragma unroll
        for (int nb = 0; nb < 4; nb++)
#pragma unroll
            for (int q = 0; q < 4; q++) sacc[nb][q] = 0.0f;

#pragma unroll
        for (int ks = 0; ks < 8; ks++) {
            const int k0 = ks * 8;
            const uint32_t a0 = f2tf32(sm.Qs[qr + g][k0 + t4]);
            const uint32_t a1 = f2tf32(sm.Qs[qr + 8 + g][k0 + t4]);
            const uint32_t a2 = f2tf32(sm.Qs[qr + g][k0 + t4 + 4]);
            const uint32_t a3 = f2tf32(sm.Qs[qr + 8 + g][k0 + t4 + 4]);
#pragma unroll
            for (int nb = 0; nb < 4; nb++) {
                const int kc = nc + nb * 8 + g;
                const uint32_t b0 = f2tf32(sm.Ks[kc][k0 + t4]);
                const uint32_t b1 = f2tf32(sm.Ks[kc][k0 + t4 + 4]);
                mma_tf32(sacc[nb], a0, a1, a2, a3, b0, b1);
            }
        }
        // store S to Ps
#pragma unroll
        for (int nb = 0; nb < 4; nb++) {
            const int c = nc + nb * 8 + 2 * t4;
            sm.Ps[qr + g][c]     = sacc[nb][0];
            sm.Ps[qr + g][c + 1] = sacc[nb][1];
            sm.Ps[qr + 8 + g][c]     = sacc[nb][2];
            sm.Ps[qr + 8 + g][c + 1] = sacc[nb][3];
        }
        __syncthreads();

        // ---- online softmax on Ps (rows of 64) ----
        float lmax = -INFINITY;
#pragma unroll
        for (int c = 0; c < 16; c++) lmax = fmaxf(lmax, sm.Ps[srow][sc0 + c]);
        sm.red[srow][sseg] = lmax;
        __syncthreads();
        if (t < 64) {
            const float mo = sm.m[t];
            float mn = fmaxf(fmaxf(sm.red[t][0], sm.red[t][1]),
                             fmaxf(sm.red[t][2], sm.red[t][3]));
            mn = fmaxf(mn, mo);
            sm.alpha[t] = __expf(mo - mn);
            sm.m[t] = mn;
        }
        __syncthreads();
        const float mn = sm.m[srow];
        float lsum = 0.0f;
#pragma unroll
        for (int c = 0; c < 16; c++) {
            const float p = __expf(sm.Ps[srow][sc0 + c] - mn);
            sm.Ps[srow][sc0 + c] = p;
            lsum += p;
        }
        sm.red[srow][sseg] = lsum;
        __syncthreads();
        if (t < 64) {
            sm.l[t] = sm.l[t] * sm.alpha[t] +
                      (sm.red[t][0] + sm.red[t][1] + sm.red[t][2] + sm.red[t][3]);
        }

        // rescale O fragments by alpha (alpha synced two barriers ago)
        const float a_lo = sm.alpha[qr + g];
        const float a_hi = sm.alpha[qr + 8 + g];
#pragma unroll
        for (int nb = 0; nb < 4; nb++) {
            obuf[nb][0] *= a_lo; obuf[nb][1] *= a_lo;
            obuf[nb][2] *= a_hi; obuf[nb][3] *= a_hi;
        }

        // ---- O += P @ V via mma.sync (k = 64 keys) ----
#pragma unroll
        for (int ks = 0; ks < 8; ks++) {
            const int k0 = ks * 8;
            const uint32_t a0 = f2tf32(sm.Ps[qr + g][k0 + t4]);
            const uint32_t a1 = f2tf32(sm.Ps[qr + 8 + g][k0 + t4]);
            const uint32_t a2 = f2tf32(sm.Ps[qr + g][k0 + t4 + 4]);
            const uint32_t a3 = f2tf32(sm.Ps[qr + 8 + g][k0 + t4 + 4]);
#pragma unroll
            for (int nb = 0; nb < 4; nb++) {
                const int dc = nc + nb * 8 + g;
                const uint32_t b0 = f2tf32(sm.Vs[k0 + t4][dc]);
                const uint32_t b1 = f2tf32(sm.Vs[k0 + t4 + 4][dc]);
                mma_tf32(obuf[nb], a0, a1, a2, a3, b0, b1);
            }
        }
    }

    __syncthreads();   // l[] final writes visible
    const float inv_lo = 1.0f / sm.l[qr + g];
    const float inv_hi = 1.0f / sm.l[qr + 8 + g];

    const int row_lo = q0 + qr + g;
    const int row_hi = row_lo + 8;
    float* o_lo = out + ((size_t)b * SEQ + row_lo) * DIM + h * HDIM;
    float* o_hi = out + ((size_t)b * SEQ + row_hi) * DIM + h * HDIM;
#pragma unroll
    for (int nb = 0; nb < 4; nb++) {
        const int c = nc + nb * 8 + 2 * t4;
        *reinterpret_cast<float2*>(o_lo + c) =
            make_float2(obuf[nb][0] * inv_lo, obuf[nb][1] * inv_lo);
        *reinterpret_cast<float2*>(o_hi + c) =
            make_float2(obuf[nb][2] * inv_hi, obuf[nb][3] * inv_hi);
    }
}

// ---------------------------------------------------------------------------
extern "C" void kernel_launch(void* const* d_in, const int* in_sizes, int n_in,
                              void* d_out, int out_size)
{
    const float* x      = (const float*)d_in[0];
    const float* w_qkv  = (const float*)d_in[1];
    const float* b_qkv  = (const float*)d_in[2];
    const float* w_proj = (const float*)d_in[3];
    const float* b_proj = (const float*)d_in[4];
    float* out = (float*)d_out;

    float *qkv, *att, *wqkvT, *wprojT;
    cudaGetSymbolAddress((void**)&qkv, g_qkv);
    cudaGetSymbolAddress((void**)&att, g_att);
    cudaGetSymbolAddress((void**)&wqkvT, g_wqkvT);
    cudaGetSymbolAddress((void**)&wprojT, g_wprojT);

    cudaFuncSetAttribute(attn_kernel, cudaFuncAttributeMaxDynamicSharedMemorySize,
                         (int)sizeof(AttnSmem));
    cudaFuncSetAttribute(gemm_mma_kernel, cudaFuncAttributeMaxDynamicSharedMemorySize,
                         GEMM_SMEM_BYTES);

    // 0) Transpose weights to [N, K]
    transpose_kernel<<<dim3(QKV_COLS / 32, DIM / 32), dim3(32, 8)>>>(
        w_qkv, wqkvT, DIM, QKV_COLS);
    transpose_kernel<<<dim3(DIM / 32, DIM / 32), dim3(32, 8)>>>(
        w_proj, wprojT, DIM, DIM);

    // 1) QKV projection (mma.sync tf32)
    gemm_mma_kernel<<<dim3(QKV_COLS / 128, ROWS / 128), 256, GEMM_SMEM_BYTES>>>(
        x, wqkvT, b_qkv, qkv, ROWS, QKV_COLS, DIM);

    // 2) Multi-head attention (mma.sync tf32)
    attn_kernel<<<dim3(SEQ / 64, BATCH * NHEAD), 256, sizeof(AttnSmem)>>>(qkv, att);

    // 3) Output projection (mma.sync tf32)
    gemm_mma_kernel<<<dim3(DIM / 128, ROWS / 128), 256, GEMM_SMEM_BYTES>>>(
        att, wprojT, b_proj, out, ROWS, DIM, DIM);
}

// round 4
// speedup vs baseline: 3.4744x; 1.1798x over previous
#include <cuda_runtime.h>
#include <cuda_bf16.h>
#include <math.h>
#include <stdint.h>

// Problem constants
#define BATCH 2
#define SEQ 2048
#define DIM 1024
#define NHEAD 16
#define HDIM 64
#define QKV_COLS (3 * DIM)          // 3072
#define ROWS (BATCH * SEQ)          // 4096
#define SCALE 0.03125f              // 1024^-0.5

// Scratch in device globals (no allocation allowed)
__device__ float g_qkv[ROWS * QKV_COLS];       // [4096, 3072]
__device__ float g_att[ROWS * DIM];            // [4096, 1024]
__device__ float g_wqkvT[QKV_COLS * DIM];      // [3072, 1024]
__device__ float g_wprojT[DIM * DIM];          // [1024, 1024]

// ---------------------------------------------------------------------------
// mma.sync helpers (base sm_103-safe; no tcgen05)
// ---------------------------------------------------------------------------
__device__ __forceinline__ uint32_t f2tf32(float f) {
    uint32_t r;
    asm("cvt.rna.tf32.f32 %0, %1;" : "=r"(r) : "f"(f));
    return r;
}

__device__ __forceinline__ void mma_tf32(float c[4],
    uint32_t a0, uint32_t a1, uint32_t a2, uint32_t a3,
    uint32_t b0, uint32_t b1)
{
    asm volatile(
        "mma.sync.aligned.m16n8k8.row.col.f32.tf32.tf32.f32 "
        "{%0,%1,%2,%3}, {%4,%5,%6,%7}, {%8,%9}, {%0,%1,%2,%3};"
        : "+f"(c[0]), "+f"(c[1]), "+f"(c[2]), "+f"(c[3])
        : "r"(a0), "r"(a1), "r"(a2), "r"(a3), "r"(b0), "r"(b1));
}

__device__ __forceinline__ uint32_t smem_u32(const void* p) {
    uint32_t a;
    asm("{ .reg .u64 t; cvta.to.shared.u64 t, %1; cvt.u32.u64 %0, t; }"
        : "=r"(a) : "l"(p));
    return a;
}

__device__ __forceinline__ void cp_async16(uint32_t dst, const void* src) {
    asm volatile("cp.async.cg.shared.global [%0], [%1], 16;"
                 :: "r"(dst), "l"(src));
}
#define CP_COMMIT() asm volatile("cp.async.commit_group;" ::: "memory")
#define CP_WAIT0()  asm volatile("cp.async.wait_group 0;" ::: "memory")
#define CP_WAIT1()  asm volatile("cp.async.wait_group 1;" ::: "memory")

// ---------------------------------------------------------------------------
// Transpose: out[n*K + k] = in[k*N + n]. block (32,8), grid (N/32, K/32).
// ---------------------------------------------------------------------------
__global__ __launch_bounds__(256) void transpose_kernel(
    const float* __restrict__ in, float* __restrict__ out, int K, int N)
{
    __shared__ float tile[32][33];
    const int n0 = blockIdx.x * 32;
    const int k0 = blockIdx.y * 32;
    const int tx = threadIdx.x, ty = threadIdx.y;
#pragma unroll
    for (int i = 0; i < 32; i += 8)
        tile[ty + i][tx] = in[(size_t)(k0 + ty + i) * N + n0 + tx];
    __syncthreads();
#pragma unroll
    for (int i = 0; i < 32; i += 8)
        out[(size_t)(n0 + ty + i) * K + k0 + tx] = tile[tx][ty + i];
}

// ---------------------------------------------------------------------------
// mma.sync tf32 GEMM: C[M,N] = A[M,K] @ Bt[N,K]^T + bias[N]
// 128x128 tile, BK=32, cp.async double-buffered, 256 threads (8 warps).
// ---------------------------------------------------------------------------
#define BK 32
#define GPAD 36
#define GSTG (128 * GPAD)
#define GEMM_SMEM_BYTES (4 * GSTG * 4)

__global__ __launch_bounds__(256) void gemm_mma_kernel(
    const float* __restrict__ A, const float* __restrict__ Bt,
    const float* __restrict__ bias, float* __restrict__ C,
    int M, int N, int K)
{
    extern __shared__ float dsm[];
    float* sA = dsm;
    float* sB = dsm + 2 * GSTG;
    const uint32_t sAb = smem_u32(sA);
    const uint32_t sBb = smem_u32(sB);

    const int t    = threadIdx.x;
    const int lane = t & 31;
    const int w    = t >> 5;
    const int wm   = w >> 2;
    const int wn   = w & 3;
    const int g    = lane >> 2;
    const int t4   = lane & 3;
    const int row0 = blockIdx.y * 128;
    const int col0 = blockIdx.x * 128;

    float acc[4][4][4];
#pragma unroll
    for (int i = 0; i < 4; i++)
#pragma unroll
        for (int j = 0; j < 4; j++)
#pragma unroll
            for (int q = 0; q < 4; q++) acc[i][j][q] = 0.0f;

    const int nchunk = K / BK;

    auto load_stage = [&](int stg, int ck) {
        const int k0 = ck * BK;
#pragma unroll
        for (int i = 0; i < 4; i++) {
            const int id = t + i * 256;
            const int r  = id >> 3;
            const int c  = id & 7;
            cp_async16(sAb + (uint32_t)((stg * GSTG + r * GPAD + c * 4) * 4),
                       A + (size_t)(row0 + r) * K + k0 + c * 4);
            cp_async16(sBb + (uint32_t)((stg * GSTG + r * GPAD + c * 4) * 4),
                       Bt + (size_t)(col0 + r) * K + k0 + c * 4);
        }
    };

    load_stage(0, 0);
    CP_COMMIT();

    for (int ck = 0; ck < nchunk; ck++) {
        if (ck + 1 < nchunk) {
            load_stage((ck + 1) & 1, ck + 1);
            CP_COMMIT();
            CP_WAIT1();
        } else {
            CP_WAIT0();
        }
        __syncthreads();

        const float* cA = sA + (ck & 1) * GSTG;
        const float* cB = sB + (ck & 1) * GSTG;

#pragma unroll
        for (int ks = 0; ks < 4; ks++) {
            const int k0 = ks * 8;
            uint32_t af[4][4];
#pragma unroll
            for (int mb = 0; mb < 4; mb++) {
                const int r = wm * 64 + mb * 16 + g;
                af[mb][0] = f2tf32(cA[r * GPAD + k0 + t4]);
                af[mb][1] = f2tf32(cA[(r + 8) * GPAD + k0 + t4]);
                af[mb][2] = f2tf32(cA[r * GPAD + k0 + t4 + 4]);
                af[mb][3] = f2tf32(cA[(r + 8) * GPAD + k0 + t4 + 4]);
            }
            uint32_t bf[4][2];
#pragma unroll
            for (int nb = 0; nb < 4; nb++) {
                const int c = wn * 32 + nb * 8 + g;
                bf[nb][0] = f2tf32(cB[c * GPAD + k0 + t4]);
                bf[nb][1] = f2tf32(cB[c * GPAD + k0 + t4 + 4]);
            }
#pragma unroll
            for (int mb = 0; mb < 4; mb++)
#pragma unroll
                for (int nb = 0; nb < 4; nb++)
                    mma_tf32(acc[mb][nb], af[mb][0], af[mb][1], af[mb][2],
                             af[mb][3], bf[nb][0], bf[nb][1]);
        }
        __syncthreads();
    }

#pragma unroll
    for (int mb = 0; mb < 4; mb++) {
        const int r = row0 + wm * 64 + mb * 16 + g;
#pragma unroll
        for (int nb = 0; nb < 4; nb++) {
            const int c = col0 + wn * 32 + nb * 8 + 2 * t4;
            const float b0 = bias[c], b1 = bias[c + 1];
            float2 v0 = make_float2(acc[mb][nb][0] + b0, acc[mb][nb][1] + b1);
            float2 v1 = make_float2(acc[mb][nb][2] + b0, acc[mb][nb][3] + b1);
            *reinterpret_cast<float2*>(C + (size_t)r * N + c) = v0;
            *reinterpret_cast<float2*>(C + (size_t)(r + 8) * N + c) = v1;
        }
    }
}

// ---------------------------------------------------------------------------
// Flash-attention v2: 256 threads, 8 warps, each warp owns 16 query rows
// (CTA = 128 q-rows). K/V pre-converted to tf32 bits in smem. Q fragments
// in registers. Warp-private online softmax (shuffle reductions).
// grid = (S/128, B*H).
// ---------------------------------------------------------------------------
#define KB_STRIDE 68
#define VB_STRIDE 72
#define PB_STRIDE 68

struct AttnSmem {
    uint32_t Kb[64][KB_STRIDE];     // K tile (tf32 bits), [key][kdim]
    uint32_t Vb[64][VB_STRIDE];     // V tile (tf32 bits), [key][dim]
    uint32_t Pb[8][16][PB_STRIDE];  // per-warp P (tf32 bits), [warp][row][key]
};

__global__ __launch_bounds__(256) void attn_kernel(
    const float* __restrict__ qkv, float* __restrict__ out)
{
    extern __shared__ char smem_raw[];
    AttnSmem& sm = *reinterpret_cast<AttnSmem*>(smem_raw);

    const int t    = threadIdx.x;
    const int lane = t & 31;
    const int w    = t >> 5;
    const int g    = lane >> 2;
    const int t4   = lane & 3;
    const int qr   = w * 16;

    const int qt = blockIdx.x;         // 0..15 (128 q-rows each)
    const int bh = blockIdx.y;
    const int b  = bh >> 4;
    const int h  = bh & 15;

    const size_t base = (size_t)b * SEQ * QKV_COLS + (size_t)h * (3 * HDIM);
    const int q0 = qt * 128;

    // ---- Q fragments in registers (scaled + converted once) ----
    uint32_t Qf[8][4];
    {
        const size_t rlo = base + (size_t)(q0 + qr + g) * QKV_COLS;
        const size_t rhi = base + (size_t)(q0 + qr + 8 + g) * QKV_COLS;
#pragma unroll
        for (int ks = 0; ks < 8; ks++) {
            const int k0 = ks * 8;
            Qf[ks][0] = f2tf32(SCALE * qkv[rlo + k0 + t4]);
            Qf[ks][1] = f2tf32(SCALE * qkv[rhi + k0 + t4]);
            Qf[ks][2] = f2tf32(SCALE * qkv[rlo + k0 + t4 + 4]);
            Qf[ks][3] = f2tf32(SCALE * qkv[rhi + k0 + t4 + 4]);
        }
    }

    float obuf[8][4];
#pragma unroll
    for (int nb = 0; nb < 8; nb++)
#pragma unroll
        for (int q = 0; q < 4; q++) obuf[nb][q] = 0.0f;

    float m_lo = -INFINITY, m_hi = -INFINITY;
    float l_lo = 0.0f, l_hi = 0.0f;

    for (int kt = 0; kt < SEQ / 64; kt++) {
        __syncthreads();   // all warps done reading Kb/Vb from previous tile
        const int k0g = kt * 64;

        // ---- stage K/V tile with conversion to tf32 bits ----
#pragma unroll
        for (int i = 0; i < 4; i++) {
            const int id = t + i * 256;          // 0..1023
            const int r  = id >> 4;              // 0..63 (key)
            const int c4 = id & 15;              // float4 col
            const float* src = qkv + base + (size_t)(k0g + r) * QKV_COLS;
            float4 kv = *reinterpret_cast<const float4*>(src + 64 + c4 * 4);
            float4 vv = *reinterpret_cast<const float4*>(src + 128 + c4 * 4);
            uint32_t* kd = &sm.Kb[r][c4 * 4];
            kd[0] = f2tf32(kv.x); kd[1] = f2tf32(kv.y);
            kd[2] = f2tf32(kv.z); kd[3] = f2tf32(kv.w);
            uint32_t* vd = &sm.Vb[r][c4 * 4];
            vd[0] = f2tf32(vv.x); vd[1] = f2tf32(vv.y);
            vd[2] = f2tf32(vv.z); vd[3] = f2tf32(vv.w);
        }
        __syncthreads();

        // ---- S = Q @ K^T ----
        float sacc[8][4];
#pragma unroll
        for (int nb = 0; nb < 8; nb++)
#pragma unroll
            for (int q = 0; q < 4; q++) sacc[nb][q] = 0.0f;

#pragma unroll
        for (int ks = 0; ks < 8; ks++) {
            const int k0 = ks * 8;
#pragma unroll
            for (int nb = 0; nb < 8; nb++) {
                const int kc = nb * 8 + g;
                const uint32_t b0 = sm.Kb[kc][k0 + t4];
                const uint32_t b1 = sm.Kb[kc][k0 + t4 + 4];
                mma_tf32(sacc[nb], Qf[ks][0], Qf[ks][1], Qf[ks][2], Qf[ks][3],
                         b0, b1);
            }
        }

        // ---- warp-private online softmax ----
        float mx_lo = -INFINITY, mx_hi = -INFINITY;
#pragma unroll
        for (int nb = 0; nb < 8; nb++) {
            mx_lo = fmaxf(mx_lo, fmaxf(sacc[nb][0], sacc[nb][1]));
            mx_hi = fmaxf(mx_hi, fmaxf(sacc[nb][2], sacc[nb][3]));
        }
        mx_lo = fmaxf(mx_lo, __shfl_xor_sync(0xffffffffu, mx_lo, 1));
        mx_lo = fmaxf(mx_lo, __shfl_xor_sync(0xffffffffu, mx_lo, 2));
        mx_hi = fmaxf(mx_hi, __shfl_xor_sync(0xffffffffu, mx_hi, 1));
        mx_hi = fmaxf(mx_hi, __shfl_xor_sync(0xffffffffu, mx_hi, 2));

        const float mn_lo = fmaxf(m_lo, mx_lo);
        const float mn_hi = fmaxf(m_hi, mx_hi);
        const float alpha_lo = __expf(m_lo - mn_lo);
        const float alpha_hi = __expf(m_hi - mn_hi);
        m_lo = mn_lo; m_hi = mn_hi;

        float sum_lo = 0.0f, sum_hi = 0.0f;
#pragma unroll
        for (int nb = 0; nb < 8; nb++) {
            const int c = nb * 8 + 2 * t4;
            const float p0 = __expf(sacc[nb][0] - mn_lo);
            const float p1 = __expf(sacc[nb][1] - mn_lo);
            const float p2 = __expf(sacc[nb][2] - mn_hi);
            const float p3 = __expf(sacc[nb][3] - mn_hi);
            sum_lo += p0 + p1;
            sum_hi += p2 + p3;
            sm.Pb[w][g][c]         = f2tf32(p0);
            sm.Pb[w][g][c + 1]     = f2tf32(p1);
            sm.Pb[w][g + 8][c]     = f2tf32(p2);
            sm.Pb[w][g + 8][c + 1] = f2tf32(p3);
        }
        sum_lo += __shfl_xor_sync(0xffffffffu, sum_lo, 1);
        sum_lo += __shfl_xor_sync(0xffffffffu, sum_lo, 2);
        sum_hi += __shfl_xor_sync(0xffffffffu, sum_hi, 1);
        sum_hi += __shfl_xor_sync(0xffffffffu, sum_hi, 2);
        l_lo = l_lo * alpha_lo + sum_lo;
        l_hi = l_hi * alpha_hi + sum_hi;

        __syncwarp();

        // rescale running O
#pragma unroll
        for (int nb = 0; nb < 8; nb++) {
            obuf[nb][0] *= alpha_lo; obuf[nb][1] *= alpha_lo;
            obuf[nb][2] *= alpha_hi; obuf[nb][3] *= alpha_hi;
        }

        // ---- O += P @ V ----
#pragma unroll
        for (int ks = 0; ks < 8; ks++) {
            const int k0 = ks * 8;
            const uint32_t a0 = sm.Pb[w][g][k0 + t4];
            const uint32_t a1 = sm.Pb[w][g + 8][k0 + t4];
            const uint32_t a2 = sm.Pb[w][g][k0 + t4 + 4];
            const uint32_t a3 = sm.Pb[w][g + 8][k0 + t4 + 4];
#pragma unroll
            for (int nb = 0; nb < 8; nb++) {
                const int dc = nb * 8 + g;
                const uint32_t b0 = sm.Vb[k0 + t4][dc];
                const uint32_t b1 = sm.Vb[k0 + t4 + 4][dc];
                mma_tf32(obuf[nb], a0, a1, a2, a3, b0, b1);
            }
        }
        __syncwarp();  // PV reads done before next tile's Pb writes
    }

    // ---- epilogue ----
    const float inv_lo = 1.0f / l_lo;
    const float inv_hi = 1.0f / l_hi;
    float* o_lo = out + ((size_t)b * SEQ + q0 + qr + g) * DIM + h * HDIM;
    float* o_hi = out + ((size_t)b * SEQ + q0 + qr + 8 + g) * DIM + h * HDIM;
#pragma unroll
    for (int nb = 0; nb < 8; nb++) {
        const int c = nb * 8 + 2 * t4;
        *reinterpret_cast<float2*>(o_lo + c) =
            make_float2(obuf[nb][0] * inv_lo, obuf[nb][1] * inv_lo);
        *reinterpret_cast<float2*>(o_hi + c) =
            make_float2(obuf[nb][2] * inv_hi, obuf[nb][3] * inv_hi);
    }
}

// ---------------------------------------------------------------------------
extern "C" void kernel_launch(void* const* d_in, const int* in_sizes, int n_in,
                              void* d_out, int out_size)
{
    const float* x      = (const float*)d_in[0];
    const float* w_qkv  = (const float*)d_in[1];
    const float* b_qkv  = (const float*)d_in[2];
    const float* w_proj = (const float*)d_in[3];
    const float* b_proj = (const float*)d_in[4];
    float* out = (float*)d_out;

    float *qkv, *att, *wqkvT, *wprojT;
    cudaGetSymbolAddress((void**)&qkv, g_qkv);
    cudaGetSymbolAddress((void**)&att, g_att);
    cudaGetSymbolAddress((void**)&wqkvT, g_wqkvT);
    cudaGetSymbolAddress((void**)&wprojT, g_wprojT);

    cudaFuncSetAttribute(attn_kernel, cudaFuncAttributeMaxDynamicSharedMemorySize,
                         (int)sizeof(AttnSmem));
    cudaFuncSetAttribute(gemm_mma_kernel, cudaFuncAttributeMaxDynamicSharedMemorySize,
                         GEMM_SMEM_BYTES);

    // 0) Transpose weights to [N, K]
    transpose_kernel<<<dim3(QKV_COLS / 32, DIM / 32), dim3(32, 8)>>>(
        w_qkv, wqkvT, DIM, QKV_COLS);
    transpose_kernel<<<dim3(DIM / 32, DIM / 32), dim3(32, 8)>>>(
        w_proj, wprojT, DIM, DIM);

    // 1) QKV projection (mma.sync tf32)
    gemm_mma_kernel<<<dim3(QKV_COLS / 128, ROWS / 128), 256, GEMM_SMEM_BYTES>>>(
        x, wqkvT, b_qkv, qkv, ROWS, QKV_COLS, DIM);

    // 2) Multi-head attention (mma.sync tf32, v2)
    attn_kernel<<<dim3(SEQ / 128, BATCH * NHEAD), 256, sizeof(AttnSmem)>>>(qkv, att);

    // 3) Output projection (mma.sync tf32)
    gemm_mma_kernel<<<dim3(DIM / 128, ROWS / 128), 256, GEMM_SMEM_BYTES>>>(
        att, wprojT, b_proj, out, ROWS, DIM, DIM);
}

// round 5
// speedup vs baseline: 3.8170x; 1.0986x over previous
#include <cuda_runtime.h>
#include <cuda_bf16.h>
#include <math.h>
#include <stdint.h>

// Problem constants
#define BATCH 2
#define SEQ 2048
#define DIM 1024
#define NHEAD 16
#define HDIM 64
#define QKV_COLS (3 * DIM)          // 3072
#define ROWS (BATCH * SEQ)          // 4096
#define SCALE 0.03125f              // 1024^-0.5

// Scratch in device globals (no allocation allowed)
__device__ float g_qkv[ROWS * QKV_COLS];       // [4096, 3072] (tf32-rounded)
__device__ float g_att[ROWS * DIM];            // [4096, 1024] (tf32-rounded)
__device__ float g_xr[ROWS * DIM];             // x, tf32-rounded
__device__ float g_wqkvT[QKV_COLS * DIM];      // [3072, 1024] (tf32-rounded)
__device__ float g_wprojT[DIM * DIM];          // [1024, 1024] (tf32-rounded)

// ---------------------------------------------------------------------------
// Helpers
// ---------------------------------------------------------------------------
__device__ __forceinline__ uint32_t f2tf32(float f) {
    uint32_t r;
    asm("cvt.rna.tf32.f32 %0, %1;" : "=r"(r) : "f"(f));
    return r;
}
__device__ __forceinline__ float tf32r(float f) {   // round-to-tf32, as float
    return __uint_as_float(f2tf32(f));
}

__device__ __forceinline__ void mma_tf32(float c[4],
    uint32_t a0, uint32_t a1, uint32_t a2, uint32_t a3,
    uint32_t b0, uint32_t b1)
{
    asm volatile(
        "mma.sync.aligned.m16n8k8.row.col.f32.tf32.tf32.f32 "
        "{%0,%1,%2,%3}, {%4,%5,%6,%7}, {%8,%9}, {%0,%1,%2,%3};"
        : "+f"(c[0]), "+f"(c[1]), "+f"(c[2]), "+f"(c[3])
        : "r"(a0), "r"(a1), "r"(a2), "r"(a3), "r"(b0), "r"(b1));
}

__device__ __forceinline__ uint32_t smem_u32(const void* p) {
    uint32_t a;
    asm("{ .reg .u64 t; cvta.to.shared.u64 t, %1; cvt.u32.u64 %0, t; }"
        : "=r"(a) : "l"(p));
    return a;
}

__device__ __forceinline__ void cp_async16(uint32_t dst, const void* src) {
    asm volatile("cp.async.cg.shared.global [%0], [%1], 16;"
                 :: "r"(dst), "l"(src));
}
#define CP_COMMIT() asm volatile("cp.async.commit_group;" ::: "memory")
#define CP_WAIT0()  asm volatile("cp.async.wait_group 0;" ::: "memory")
#define CP_WAIT1()  asm volatile("cp.async.wait_group 1;" ::: "memory")

// ---------------------------------------------------------------------------
// Elementwise tf32 rounding: out[i] = tf32(in[i]) (float4 vectorized)
// ---------------------------------------------------------------------------
__global__ __launch_bounds__(256) void cvt_tf32_kernel(
    const float* __restrict__ in, float* __restrict__ out, int n4)
{
    const int i = blockIdx.x * 256 + threadIdx.x;
    if (i < n4) {
        float4 v = reinterpret_cast<const float4*>(in)[i];
        v.x = tf32r(v.x); v.y = tf32r(v.y);
        v.z = tf32r(v.z); v.w = tf32r(v.w);
        reinterpret_cast<float4*>(out)[i] = v;
    }
}

// ---------------------------------------------------------------------------
// Transpose + tf32 round: out[n*K + k] = tf32(in[k*N + n]).
// ---------------------------------------------------------------------------
__global__ __launch_bounds__(256) void transpose_kernel(
    const float* __restrict__ in, float* __restrict__ out, int K, int N)
{
    __shared__ float tile[32][33];
    const int n0 = blockIdx.x * 32;
    const int k0 = blockIdx.y * 32;
    const int tx = threadIdx.x, ty = threadIdx.y;
#pragma unroll
    for (int i = 0; i < 32; i += 8)
        tile[ty + i][tx] = tf32r(in[(size_t)(k0 + ty + i) * N + n0 + tx]);
    __syncthreads();
#pragma unroll
    for (int i = 0; i < 32; i += 8)
        out[(size_t)(n0 + ty + i) * K + k0 + tx] = tile[tx][ty + i];
}

// ---------------------------------------------------------------------------
// mma.sync tf32 GEMM: C[M,N] = A[M,K] @ Bt[N,K]^T + bias[N]
// A and Bt are PRE-ROUNDED to tf32 — fragments are raw bit loads.
// 128x128 tile, BK=32, cp.async double-buffered, 256 threads.
// ROUND_OUT: round output to tf32 (for buffers consumed by later tf32 stages).
// ---------------------------------------------------------------------------
#define BK 32
#define GPAD 36
#define GSTG (128 * GPAD)
#define GEMM_SMEM_BYTES (4 * GSTG * 4)

template <bool ROUND_OUT>
__global__ __launch_bounds__(256) void gemm_mma_kernel(
    const float* __restrict__ A, const float* __restrict__ Bt,
    const float* __restrict__ bias, float* __restrict__ C,
    int M, int N, int K)
{
    extern __shared__ float dsm[];
    float* sA = dsm;
    float* sB = dsm + 2 * GSTG;
    const uint32_t sAb = smem_u32(sA);
    const uint32_t sBb = smem_u32(sB);

    const int t    = threadIdx.x;
    const int lane = t & 31;
    const int w    = t >> 5;
    const int wm   = w >> 2;
    const int wn   = w & 3;
    const int g    = lane >> 2;
    const int t4   = lane & 3;
    const int row0 = blockIdx.y * 128;
    const int col0 = blockIdx.x * 128;

    float acc[4][4][4];
#pragma unroll
    for (int i = 0; i < 4; i++)
#pragma unroll
        for (int j = 0; j < 4; j++)
#pragma unroll
            for (int q = 0; q < 4; q++) acc[i][j][q] = 0.0f;

    const int nchunk = K / BK;

    auto load_stage = [&](int stg, int ck) {
        const int k0 = ck * BK;
#pragma unroll
        for (int i = 0; i < 4; i++) {
            const int id = t + i * 256;
            const int r  = id >> 3;
            const int c  = id & 7;
            cp_async16(sAb + (uint32_t)((stg * GSTG + r * GPAD + c * 4) * 4),
                       A + (size_t)(row0 + r) * K + k0 + c * 4);
            cp_async16(sBb + (uint32_t)((stg * GSTG + r * GPAD + c * 4) * 4),
                       Bt + (size_t)(col0 + r) * K + k0 + c * 4);
        }
    };

    load_stage(0, 0);
    CP_COMMIT();

    for (int ck = 0; ck < nchunk; ck++) {
        if (ck + 1 < nchunk) {
            load_stage((ck + 1) & 1, ck + 1);
            CP_COMMIT();
            CP_WAIT1();
        } else {
            CP_WAIT0();
        }
        __syncthreads();

        const uint32_t* cA =
            reinterpret_cast<const uint32_t*>(sA + (ck & 1) * GSTG);
        const uint32_t* cB =
            reinterpret_cast<const uint32_t*>(sB + (ck & 1) * GSTG);

#pragma unroll
        for (int ks = 0; ks < 4; ks++) {
            const int k0 = ks * 8;
            uint32_t af[4][4];
#pragma unroll
            for (int mb = 0; mb < 4; mb++) {
                const int r = wm * 64 + mb * 16 + g;
                af[mb][0] = cA[r * GPAD + k0 + t4];
                af[mb][1] = cA[(r + 8) * GPAD + k0 + t4];
                af[mb][2] = cA[r * GPAD + k0 + t4 + 4];
                af[mb][3] = cA[(r + 8) * GPAD + k0 + t4 + 4];
            }
            uint32_t bf[4][2];
#pragma unroll
            for (int nb = 0; nb < 4; nb++) {
                const int c = wn * 32 + nb * 8 + g;
                bf[nb][0] = cB[c * GPAD + k0 + t4];
                bf[nb][1] = cB[c * GPAD + k0 + t4 + 4];
            }
#pragma unroll
            for (int mb = 0; mb < 4; mb++)
#pragma unroll
                for (int nb = 0; nb < 4; nb++)
                    mma_tf32(acc[mb][nb], af[mb][0], af[mb][1], af[mb][2],
                             af[mb][3], bf[nb][0], bf[nb][1]);
        }
        __syncthreads();
    }

#pragma unroll
    for (int mb = 0; mb < 4; mb++) {
        const int r = row0 + wm * 64 + mb * 16 + g;
#pragma unroll
        for (int nb = 0; nb < 4; nb++) {
            const int c = col0 + wn * 32 + nb * 8 + 2 * t4;
            const float b0 = bias[c], b1 = bias[c + 1];
            float2 v0, v1;
            if (ROUND_OUT) {
                v0 = make_float2(tf32r(acc[mb][nb][0] + b0),
                                 tf32r(acc[mb][nb][1] + b1));
                v1 = make_float2(tf32r(acc[mb][nb][2] + b0),
                                 tf32r(acc[mb][nb][3] + b1));
            } else {
                v0 = make_float2(acc[mb][nb][0] + b0, acc[mb][nb][1] + b1);
                v1 = make_float2(acc[mb][nb][2] + b0, acc[mb][nb][3] + b1);
            }
            *reinterpret_cast<float2*>(C + (size_t)r * N + c) = v0;
            *reinterpret_cast<float2*>(C + (size_t)(r + 8) * N + c) = v1;
        }
    }
}

// ---------------------------------------------------------------------------
// Flash-attention v3: qkv is pre-rounded to tf32, so staging is a raw copy.
// K/V double-buffered in smem with a register-pipelined prefetch (LDG for
// tile kt+1 issued while computing tile kt). One barrier per key tile.
// 8 warps x 16 query rows = 128 q-rows per CTA. grid = (S/128, B*H).
// ---------------------------------------------------------------------------
#define KB_STRIDE 68
#define VB_STRIDE 72
#define PB_STRIDE 68

struct AttnSmem {
    uint32_t Kb[2][64][KB_STRIDE];    // K tiles (tf32 bits)
    uint32_t Vb[2][64][VB_STRIDE];    // V tiles (tf32 bits)
    uint32_t Pb[8][16][PB_STRIDE];    // per-warp P (tf32 bits)
};

__global__ __launch_bounds__(256) void attn_kernel(
    const float* __restrict__ qkv, float* __restrict__ out)
{
    extern __shared__ char smem_raw[];
    AttnSmem& sm = *reinterpret_cast<AttnSmem*>(smem_raw);

    const int t    = threadIdx.x;
    const int lane = t & 31;
    const int w    = t >> 5;
    const int g    = lane >> 2;
    const int t4   = lane & 3;
    const int qr   = w * 16;

    const int qt = blockIdx.x;
    const int bh = blockIdx.y;
    const int b  = bh >> 4;
    const int h  = bh & 15;

    const size_t base = (size_t)b * SEQ * QKV_COLS + (size_t)h * (3 * HDIM);
    const int q0 = qt * 128;

    // ---- Q fragments in registers (qkv pre-rounded; SCALE=2^-5 exact) ----
    uint32_t Qf[8][4];
    {
        const size_t rlo = base + (size_t)(q0 + qr + g) * QKV_COLS;
        const size_t rhi = base + (size_t)(q0 + qr + 8 + g) * QKV_COLS;
#pragma unroll
        for (int ks = 0; ks < 8; ks++) {
            const int k0 = ks * 8;
            Qf[ks][0] = __float_as_uint(SCALE * qkv[rlo + k0 + t4]);
            Qf[ks][1] = __float_as_uint(SCALE * qkv[rhi + k0 + t4]);
            Qf[ks][2] = __float_as_uint(SCALE * qkv[rlo + k0 + t4 + 4]);
            Qf[ks][3] = __float_as_uint(SCALE * qkv[rhi + k0 + t4 + 4]);
        }
    }

    float obuf[8][4];
#pragma unroll
    for (int nb = 0; nb < 8; nb++)
#pragma unroll
        for (int q = 0; q < 4; q++) obuf[nb][q] = 0.0f;

    float m_lo = -INFINITY, m_hi = -INFINITY;
    float l_lo = 0.0f, l_hi = 0.0f;

    // Per-thread staging registers (one tile = 4 K-float4 + 4 V-float4)
    uint4 kreg[4], vreg[4];

    auto load_tile = [&](int kt) {
        const int k0g = kt * 64;
#pragma unroll
        for (int i = 0; i < 4; i++) {
            const int id = t + i * 256;
            const int r  = id >> 4;
            const int c4 = id & 15;
            const float* src = qkv + base + (size_t)(k0g + r) * QKV_COLS;
            kreg[i] = *reinterpret_cast<const uint4*>(src + 64 + c4 * 4);
            vreg[i] = *reinterpret_cast<const uint4*>(src + 128 + c4 * 4);
        }
    };
    auto sts_tile = [&](int bufi) {
#pragma unroll
        for (int i = 0; i < 4; i++) {
            const int id = t + i * 256;
            const int r  = id >> 4;
            const int c4 = id & 15;
            *reinterpret_cast<uint4*>(&sm.Kb[bufi][r][c4 * 4]) = kreg[i];
            *reinterpret_cast<uint4*>(&sm.Vb[bufi][r][c4 * 4]) = vreg[i];
        }
    };

    load_tile(0);

    for (int kt = 0; kt < SEQ / 64; kt++) {
        const int cur = kt & 1;
        sts_tile(cur);
        __syncthreads();
        if (kt + 1 < SEQ / 64) load_tile(kt + 1);   // prefetch, consumed next iter

        // ---- S = Q @ K^T ----
        float sacc[8][4];
#pragma unroll
        for (int nb = 0; nb < 8; nb++)
#pragma unroll
            for (int q = 0; q < 4; q++) sacc[nb][q] = 0.0f;

#pragma unroll
        for (int ks = 0; ks < 8; ks++) {
            const int k0 = ks * 8;
#pragma unroll
            for (int nb = 0; nb < 8; nb++) {
                const int kc = nb * 8 + g;
                const uint32_t b0 = sm.Kb[cur][kc][k0 + t4];
                const uint32_t b1 = sm.Kb[cur][kc][k0 + t4 + 4];
                mma_tf32(sacc[nb], Qf[ks][0], Qf[ks][1], Qf[ks][2], Qf[ks][3],
                         b0, b1);
            }
        }

        // ---- warp-private online softmax ----
        float mx_lo = -INFINITY, mx_hi = -INFINITY;
#pragma unroll
        for (int nb = 0; nb < 8; nb++) {
            mx_lo = fmaxf(mx_lo, fmaxf(sacc[nb][0], sacc[nb][1]));
            mx_hi = fmaxf(mx_hi, fmaxf(sacc[nb][2], sacc[nb][3]));
        }
        mx_lo = fmaxf(mx_lo, __shfl_xor_sync(0xffffffffu, mx_lo, 1));
        mx_lo = fmaxf(mx_lo, __shfl_xor_sync(0xffffffffu, mx_lo, 2));
        mx_hi = fmaxf(mx_hi, __shfl_xor_sync(0xffffffffu, mx_hi, 1));
        mx_hi = fmaxf(mx_hi, __shfl_xor_sync(0xffffffffu, mx_hi, 2));

        const float mn_lo = fmaxf(m_lo, mx_lo);
        const float mn_hi = fmaxf(m_hi, mx_hi);
        const float alpha_lo = __expf(m_lo - mn_lo);
        const float alpha_hi = __expf(m_hi - mn_hi);
        m_lo = mn_lo; m_hi = mn_hi;

        float sum_lo = 0.0f, sum_hi = 0.0f;
#pragma unroll
        for (int nb = 0; nb < 8; nb++) {
            const int c = nb * 8 + 2 * t4;
            const float p0 = __expf(sacc[nb][0] - mn_lo);
            const float p1 = __expf(sacc[nb][1] - mn_lo);
            const float p2 = __expf(sacc[nb][2] - mn_hi);
            const float p3 = __expf(sacc[nb][3] - mn_hi);
            sum_lo += p0 + p1;
            sum_hi += p2 + p3;
            sm.Pb[w][g][c]         = f2tf32(p0);
            sm.Pb[w][g][c + 1]     = f2tf32(p1);
            sm.Pb[w][g + 8][c]     = f2tf32(p2);
            sm.Pb[w][g + 8][c + 1] = f2tf32(p3);
        }
        sum_lo += __shfl_xor_sync(0xffffffffu, sum_lo, 1);
        sum_lo += __shfl_xor_sync(0xffffffffu, sum_lo, 2);
        sum_hi += __shfl_xor_sync(0xffffffffu, sum_hi, 1);
        sum_hi += __shfl_xor_sync(0xffffffffu, sum_hi, 2);
        l_lo = l_lo * alpha_lo + sum_lo;
        l_hi = l_hi * alpha_hi + sum_hi;

        __syncwarp();

#pragma unroll
        for (int nb = 0; nb < 8; nb++) {
            obuf[nb][0] *= alpha_lo; obuf[nb][1] *= alpha_lo;
            obuf[nb][2] *= alpha_hi; obuf[nb][3] *= alpha_hi;
        }

        // ---- O += P @ V ----
#pragma unroll
        for (int ks = 0; ks < 8; ks++) {
            const int k0 = ks * 8;
            const uint32_t a0 = sm.Pb[w][g][k0 + t4];
            const uint32_t a1 = sm.Pb[w][g + 8][k0 + t4];
            const uint32_t a2 = sm.Pb[w][g][k0 + t4 + 4];
            const uint32_t a3 = sm.Pb[w][g + 8][k0 + t4 + 4];
#pragma unroll
            for (int nb = 0; nb < 8; nb++) {
                const int dc = nb * 8 + g;
                const uint32_t b0 = sm.Vb[cur][k0 + t4][dc];
                const uint32_t b1 = sm.Vb[cur][k0 + t4 + 4][dc];
                mma_tf32(obuf[nb], a0, a1, a2, a3, b0, b1);
            }
        }
        __syncwarp();
    }

    // ---- epilogue (tf32-rounded: consumed by tf32 proj GEMM) ----
    const float inv_lo = 1.0f / l_lo;
    const float inv_hi = 1.0f / l_hi;
    float* o_lo = out + ((size_t)b * SEQ + q0 + qr + g) * DIM + h * HDIM;
    float* o_hi = out + ((size_t)b * SEQ + q0 + qr + 8 + g) * DIM + h * HDIM;
#pragma unroll
    for (int nb = 0; nb < 8; nb++) {
        const int c = nb * 8 + 2 * t4;
        *reinterpret_cast<float2*>(o_lo + c) =
            make_float2(tf32r(obuf[nb][0] * inv_lo), tf32r(obuf[nb][1] * inv_lo));
        *reinterpret_cast<float2*>(o_hi + c) =
            make_float2(tf32r(obuf[nb][2] * inv_hi), tf32r(obuf[nb][3] * inv_hi));
    }
}

// ---------------------------------------------------------------------------
extern "C" void kernel_launch(void* const* d_in, const int* in_sizes, int n_in,
                              void* d_out, int out_size)
{
    const float* x      = (const float*)d_in[0];
    const float* w_qkv  = (const float*)d_in[1];
    const float* b_qkv  = (const float*)d_in[2];
    const float* w_proj = (const float*)d_in[3];
    const float* b_proj = (const float*)d_in[4];
    float* out = (float*)d_out;

    float *qkv, *att, *xr, *wqkvT, *wprojT;
    cudaGetSymbolAddress((void**)&qkv, g_qkv);
    cudaGetSymbolAddress((void**)&att, g_att);
    cudaGetSymbolAddress((void**)&xr, g_xr);
    cudaGetSymbolAddress((void**)&wqkvT, g_wqkvT);
    cudaGetSymbolAddress((void**)&wprojT, g_wprojT);

    cudaFuncSetAttribute(attn_kernel, cudaFuncAttributeMaxDynamicSharedMemorySize,
                         (int)sizeof(AttnSmem));
    cudaFuncSetAttribute(gemm_mma_kernel<true>,
                         cudaFuncAttributeMaxDynamicSharedMemorySize, GEMM_SMEM_BYTES);
    cudaFuncSetAttribute(gemm_mma_kernel<false>,
                         cudaFuncAttributeMaxDynamicSharedMemorySize, GEMM_SMEM_BYTES);

    // 0) Producers: round everything once (numerically identical to
    //    per-fragment cvt the consumers used before).
    cvt_tf32_kernel<<<(ROWS * DIM / 4 + 255) / 256, 256>>>(x, xr, ROWS * DIM / 4);
    transpose_kernel<<<dim3(QKV_COLS / 32, DIM / 32), dim3(32, 8)>>>(
        w_qkv, wqkvT, DIM, QKV_COLS);
    transpose_kernel<<<dim3(DIM / 32, DIM / 32), dim3(32, 8)>>>(
        w_proj, wprojT, DIM, DIM);

    // 1) QKV projection (rounds output for attention)
    gemm_mma_kernel<true><<<dim3(QKV_COLS / 128, ROWS / 128), 256, GEMM_SMEM_BYTES>>>(
        xr, wqkvT, b_qkv, qkv, ROWS, QKV_COLS, DIM);

    // 2) Multi-head attention
    attn_kernel<<<dim3(SEQ / 128, BATCH * NHEAD), 256, sizeof(AttnSmem)>>>(qkv, att);

    // 3) Output projection (full fp32 output)
    gemm_mma_kernel<false><<<dim3(DIM / 128, ROWS / 128), 256, GEMM_SMEM_BYTES>>>(
        att, wprojT, b_proj, out, ROWS, DIM, DIM);
}

// round 7
// speedup vs baseline: 4.1851x; 1.0964x over previous
#include <cuda_runtime.h>
#include <cuda_bf16.h>
#include <math.h>
#include <stdint.h>

// Problem constants
#define BATCH 2
#define SEQ 2048
#define DIM 1024
#define NHEAD 16
#define HDIM 64
#define QKV_COLS (3 * DIM)          // 3072
#define ROWS (BATCH * SEQ)          // 4096
#define SCALE 0.03125f              // 1024^-0.5

// Scratch in device globals (no allocation allowed)
__device__ float g_qkv[ROWS * QKV_COLS];       // [4096, 3072] (tf32-rounded)
__device__ float g_att[ROWS * DIM];            // [4096, 1024] (tf32-rounded)
__device__ float g_xr[ROWS * DIM];             // x, tf32-rounded
__device__ float g_wqkvT[QKV_COLS * DIM];      // [3072, 1024] (tf32-rounded)
__device__ float g_wprojT[DIM * DIM];          // [1024, 1024] (tf32-rounded)

// ---------------------------------------------------------------------------
// Helpers
// ---------------------------------------------------------------------------
__device__ __forceinline__ uint32_t f2tf32(float f) {
    uint32_t r;
    asm("cvt.rna.tf32.f32 %0, %1;" : "=r"(r) : "f"(f));
    return r;
}
__device__ __forceinline__ float tf32r(float f) {
    return __uint_as_float(f2tf32(f));
}

__device__ __forceinline__ void mma_tf32(float c[4],
    uint32_t a0, uint32_t a1, uint32_t a2, uint32_t a3,
    uint32_t b0, uint32_t b1)
{
    asm volatile(
        "mma.sync.aligned.m16n8k8.row.col.f32.tf32.tf32.f32 "
        "{%0,%1,%2,%3}, {%4,%5,%6,%7}, {%8,%9}, {%0,%1,%2,%3};"
        : "+f"(c[0]), "+f"(c[1]), "+f"(c[2]), "+f"(c[3])
        : "r"(a0), "r"(a1), "r"(a2), "r"(a3), "r"(b0), "r"(b1));
}

__device__ __forceinline__ uint32_t smem_u32(const void* p) {
    uint32_t a;
    asm("{ .reg .u64 t; cvta.to.shared.u64 t, %1; cvt.u32.u64 %0, t; }"
        : "=r"(a) : "l"(p));
    return a;
}

__device__ __forceinline__ void cp_async16(uint32_t dst, const void* src) {
    asm volatile("cp.async.cg.shared.global [%0], [%1], 16;"
                 :: "r"(dst), "l"(src));
}
#define CP_COMMIT() asm volatile("cp.async.commit_group;" ::: "memory")
#define CP_WAIT0()  asm volatile("cp.async.wait_group 0;" ::: "memory")
#define CP_WAIT1()  asm volatile("cp.async.wait_group 1;" ::: "memory")

// ---------------------------------------------------------------------------
// Elementwise tf32 rounding
// ---------------------------------------------------------------------------
__global__ __launch_bounds__(256) void cvt_tf32_kernel(
    const float* __restrict__ in, float* __restrict__ out, int n4)
{
    const int i = blockIdx.x * 256 + threadIdx.x;
    if (i < n4) {
        float4 v = reinterpret_cast<const float4*>(in)[i];
        v.x = tf32r(v.x); v.y = tf32r(v.y);
        v.z = tf32r(v.z); v.w = tf32r(v.w);
        reinterpret_cast<float4*>(out)[i] = v;
    }
}

// ---------------------------------------------------------------------------
// Transpose + tf32 round: out[n*K + k] = tf32(in[k*N + n]).
// ---------------------------------------------------------------------------
__global__ __launch_bounds__(256) void transpose_kernel(
    const float* __restrict__ in, float* __restrict__ out, int K, int N)
{
    __shared__ float tile[32][33];
    const int n0 = blockIdx.x * 32;
    const int k0 = blockIdx.y * 32;
    const int tx = threadIdx.x, ty = threadIdx.y;
#pragma unroll
    for (int i = 0; i < 32; i += 8)
        tile[ty + i][tx] = tf32r(in[(size_t)(k0 + ty + i) * N + n0 + tx]);
    __syncthreads();
#pragma unroll
    for (int i = 0; i < 32; i += 8)
        out[(size_t)(n0 + ty + i) * K + k0 + tx] = tile[tx][ty + i];
}

// ---------------------------------------------------------------------------
// mma.sync tf32 GEMM: C[M,N] = A[M,K] @ Bt[N,K]^T + bias[N]
// Pre-rounded inputs. 128x128 tile, BK=32, cp.async double-buffered,
// 256 threads, min 2 CTAs/SM.
// ---------------------------------------------------------------------------
#define BK 32
#define GPAD 36
#define GSTG (128 * GPAD)
#define GEMM_SMEM_BYTES (4 * GSTG * 4)

template <bool ROUND_OUT>
__global__ __launch_bounds__(256, 2) void gemm_mma_kernel(
    const float* __restrict__ A, const float* __restrict__ Bt,
    const float* __restrict__ bias, float* __restrict__ C,
    int M, int N, int K)
{
    extern __shared__ float dsm[];
    float* sA = dsm;
    float* sB = dsm + 2 * GSTG;
    const uint32_t sAb = smem_u32(sA);
    const uint32_t sBb = smem_u32(sB);

    const int t    = threadIdx.x;
    const int lane = t & 31;
    const int w    = t >> 5;
    const int wm   = w >> 2;
    const int wn   = w & 3;
    const int g    = lane >> 2;
    const int t4   = lane & 3;
    const int row0 = blockIdx.y * 128;
    const int col0 = blockIdx.x * 128;

    float acc[4][4][4];
#pragma unroll
    for (int i = 0; i < 4; i++)
#pragma unroll
        for (int j = 0; j < 4; j++)
#pragma unroll
            for (int q = 0; q < 4; q++) acc[i][j][q] = 0.0f;

    const int nchunk = K / BK;

    auto load_stage = [&](int stg, int ck) {
        const int k0 = ck * BK;
#pragma unroll
        for (int i = 0; i < 4; i++) {
            const int id = t + i * 256;
            const int r  = id >> 3;
            const int c  = id & 7;
            cp_async16(sAb + (uint32_t)((stg * GSTG + r * GPAD + c * 4) * 4),
                       A + (size_t)(row0 + r) * K + k0 + c * 4);
            cp_async16(sBb + (uint32_t)((stg * GSTG + r * GPAD + c * 4) * 4),
                       Bt + (size_t)(col0 + r) * K + k0 + c * 4);
        }
    };

    load_stage(0, 0);
    CP_COMMIT();

    for (int ck = 0; ck < nchunk; ck++) {
        if (ck + 1 < nchunk) {
            load_stage((ck + 1) & 1, ck + 1);
            CP_COMMIT();
            CP_WAIT1();
        } else {
            CP_WAIT0();
        }
        __syncthreads();

        const uint32_t* cA =
            reinterpret_cast<const uint32_t*>(sA + (ck & 1) * GSTG);
        const uint32_t* cB =
            reinterpret_cast<const uint32_t*>(sB + (ck & 1) * GSTG);

#pragma unroll
        for (int ks = 0; ks < 4; ks++) {
            const int k0 = ks * 8;
            uint32_t af[4][4];
#pragma unroll
            for (int mb = 0; mb < 4; mb++) {
                const int r = wm * 64 + mb * 16 + g;
                af[mb][0] = cA[r * GPAD + k0 + t4];
                af[mb][1] = cA[(r + 8) * GPAD + k0 + t4];
                af[mb][2] = cA[r * GPAD + k0 + t4 + 4];
                af[mb][3] = cA[(r + 8) * GPAD + k0 + t4 + 4];
            }
            uint32_t bf[4][2];
#pragma unroll
            for (int nb = 0; nb < 4; nb++) {
                const int c = wn * 32 + nb * 8 + g;
                bf[nb][0] = cB[c * GPAD + k0 + t4];
                bf[nb][1] = cB[c * GPAD + k0 + t4 + 4];
            }
#pragma unroll
            for (int mb = 0; mb < 4; mb++)
#pragma unroll
                for (int nb = 0; nb < 4; nb++)
                    mma_tf32(acc[mb][nb], af[mb][0], af[mb][1], af[mb][2],
                             af[mb][3], bf[nb][0], bf[nb][1]);
        }
        __syncthreads();
    }

#pragma unroll
    for (int mb = 0; mb < 4; mb++) {
        const int r = row0 + wm * 64 + mb * 16 + g;
#pragma unroll
        for (int nb = 0; nb < 4; nb++) {
            const int c = col0 + wn * 32 + nb * 8 + 2 * t4;
            const float b0 = bias[c], b1 = bias[c + 1];
            float2 v0, v1;
            if (ROUND_OUT) {
                v0 = make_float2(tf32r(acc[mb][nb][0] + b0),
                                 tf32r(acc[mb][nb][1] + b1));
                v1 = make_float2(tf32r(acc[mb][nb][2] + b0),
                                 tf32r(acc[mb][nb][3] + b1));
            } else {
                v0 = make_float2(acc[mb][nb][0] + b0, acc[mb][nb][1] + b1);
                v1 = make_float2(acc[mb][nb][2] + b0, acc[mb][nb][3] + b1);
            }
            *reinterpret_cast<float2*>(C + (size_t)r * N + c) = v0;
            *reinterpret_cast<float2*>(C + (size_t)(r + 8) * N + c) = v1;
        }
    }
}

// ---------------------------------------------------------------------------
// Flash-attention v4b: cp.async double-buffered K/V staging (FULL tile:
// 4 float4 per tensor per thread), 2 CTAs/SM. 8 warps x 16 query rows.
// grid = (S/128, B*H).
// ---------------------------------------------------------------------------
#define KB_STRIDE 68
#define VB_STRIDE 72
#define PB_STRIDE 68

struct AttnSmem {
    uint32_t Kb[2][64][KB_STRIDE];
    uint32_t Vb[2][64][VB_STRIDE];
    uint32_t Pb[8][16][PB_STRIDE];
};

__global__ __launch_bounds__(256, 2) void attn_kernel(
    const float* __restrict__ qkv, float* __restrict__ out)
{
    extern __shared__ char smem_raw[];
    AttnSmem& sm = *reinterpret_cast<AttnSmem*>(smem_raw);

    const int t    = threadIdx.x;
    const int lane = t & 31;
    const int w    = t >> 5;
    const int g    = lane >> 2;
    const int t4   = lane & 3;
    const int qr   = w * 16;

    const int qt = blockIdx.x;
    const int bh = blockIdx.y;
    const int b  = bh >> 4;
    const int h  = bh & 15;

    const size_t base = (size_t)b * SEQ * QKV_COLS + (size_t)h * (3 * HDIM);
    const int q0 = qt * 128;

    // cp.async staging: 64 rows x 16 float4 per tensor; 4 threads/row,
    // 4 float4 per tensor per thread (cols sc4, sc4+16, sc4+32, sc4+48).
    const int sr  = t >> 2;              // key row 0..63
    const int sc4 = (t & 3) * 4;         // starting float col: 0,4,8,12

    const uint32_t kbase = smem_u32(&sm.Kb[0][sr][sc4]);
    const uint32_t vbase = smem_u32(&sm.Vb[0][sr][sc4]);
    const uint32_t kbufstride = (uint32_t)(64 * KB_STRIDE * 4);
    const uint32_t vbufstride = (uint32_t)(64 * VB_STRIDE * 4);

    auto prefetch = [&](int kt, int bufi) {
        const float* src = qkv + base + (size_t)(kt * 64 + sr) * QKV_COLS;
        const uint32_t kd = kbase + bufi * kbufstride;
        const uint32_t vd = vbase + bufi * vbufstride;
#pragma unroll
        for (int i = 0; i < 4; i++) {
            cp_async16(kd + i * 64, src + 64 + sc4 + i * 16);
            cp_async16(vd + i * 64, src + 128 + sc4 + i * 16);
        }
        CP_COMMIT();
    };

    // ---- Q fragments in registers (pre-rounded; SCALE=2^-5 exact) ----
    uint32_t Qf[8][4];
    {
        const size_t rlo = base + (size_t)(q0 + qr + g) * QKV_COLS;
        const size_t rhi = base + (size_t)(q0 + qr + 8 + g) * QKV_COLS;
#pragma unroll
        for (int ks = 0; ks < 8; ks++) {
            const int k0 = ks * 8;
            Qf[ks][0] = __float_as_uint(SCALE * qkv[rlo + k0 + t4]);
            Qf[ks][1] = __float_as_uint(SCALE * qkv[rhi + k0 + t4]);
            Qf[ks][2] = __float_as_uint(SCALE * qkv[rlo + k0 + t4 + 4]);
            Qf[ks][3] = __float_as_uint(SCALE * qkv[rhi + k0 + t4 + 4]);
        }
    }

    float obuf[8][4];
#pragma unroll
    for (int nb = 0; nb < 8; nb++)
#pragma unroll
        for (int q = 0; q < 4; q++) obuf[nb][q] = 0.0f;

    float m_lo = -INFINITY, m_hi = -INFINITY;
    float l_lo = 0.0f, l_hi = 0.0f;

    prefetch(0, 0);

    const int NT = SEQ / 64;
    for (int kt = 0; kt < NT; kt++) {
        const int cur = kt & 1;
        CP_WAIT0();            // tile kt landed
        __syncthreads();       // visible to all; all warps done with buf cur^1
        if (kt + 1 < NT) prefetch(kt + 1, cur ^ 1);

        // ---- S = Q @ K^T ----
        float sacc[8][4];
#pragma unroll
        for (int nb = 0; nb < 8; nb++)
#pragma unroll
            for (int q = 0; q < 4; q++) sacc[nb][q] = 0.0f;

#pragma unroll
        for (int ks = 0; ks < 8; ks++) {
            const int k0 = ks * 8;
#pragma unroll
            for (int nb = 0; nb < 8; nb++) {
                const int kc = nb * 8 + g;
                const uint32_t b0 = sm.Kb[cur][kc][k0 + t4];
                const uint32_t b1 = sm.Kb[cur][kc][k0 + t4 + 4];
                mma_tf32(sacc[nb], Qf[ks][0], Qf[ks][1], Qf[ks][2], Qf[ks][3],
                         b0, b1);
            }
        }

        // ---- warp-private online softmax ----
        float mx_lo = -INFINITY, mx_hi = -INFINITY;
#pragma unroll
        for (int nb = 0; nb < 8; nb++) {
            mx_lo = fmaxf(mx_lo, fmaxf(sacc[nb][0], sacc[nb][1]));
            mx_hi = fmaxf(mx_hi, fmaxf(sacc[nb][2], sacc[nb][3]));
        }
        mx_lo = fmaxf(mx_lo, __shfl_xor_sync(0xffffffffu, mx_lo, 1));
        mx_lo = fmaxf(mx_lo, __shfl_xor_sync(0xffffffffu, mx_lo, 2));
        mx_hi = fmaxf(mx_hi, __shfl_xor_sync(0xffffffffu, mx_hi, 1));
        mx_hi = fmaxf(mx_hi, __shfl_xor_sync(0xffffffffu, mx_hi, 2));

        const float mn_lo = fmaxf(m_lo, mx_lo);
        const float mn_hi = fmaxf(m_hi, mx_hi);
        const float alpha_lo = __expf(m_lo - mn_lo);
        const float alpha_hi = __expf(m_hi - mn_hi);
        m_lo = mn_lo; m_hi = mn_hi;

        float sum_lo = 0.0f, sum_hi = 0.0f;
#pragma unroll
        for (int nb = 0; nb < 8; nb++) {
            const int c = nb * 8 + 2 * t4;
            const float p0 = __expf(sacc[nb][0] - mn_lo);
            const float p1 = __expf(sacc[nb][1] - mn_lo);
            const float p2 = __expf(sacc[nb][2] - mn_hi);
            const float p3 = __expf(sacc[nb][3] - mn_hi);
            sum_lo += p0 + p1;
            sum_hi += p2 + p3;
            sm.Pb[w][g][c]         = f2tf32(p0);
            sm.Pb[w][g][c + 1]     = f2tf32(p1);
            sm.Pb[w][g + 8][c]     = f2tf32(p2);
            sm.Pb[w][g + 8][c + 1] = f2tf32(p3);
        }
        sum_lo += __shfl_xor_sync(0xffffffffu, sum_lo, 1);
        sum_lo += __shfl_xor_sync(0xffffffffu, sum_lo, 2);
        sum_hi += __shfl_xor_sync(0xffffffffu, sum_hi, 1);
        sum_hi += __shfl_xor_sync(0xffffffffu, sum_hi, 2);
        l_lo = l_lo * alpha_lo + sum_lo;
        l_hi = l_hi * alpha_hi + sum_hi;

        __syncwarp();

#pragma unroll
        for (int nb = 0; nb < 8; nb++) {
            obuf[nb][0] *= alpha_lo; obuf[nb][1] *= alpha_lo;
            obuf[nb][2] *= alpha_hi; obuf[nb][3] *= alpha_hi;
        }

        // ---- O += P @ V ----
#pragma unroll
        for (int ks = 0; ks < 8; ks++) {
            const int k0 = ks * 8;
            const uint32_t a0 = sm.Pb[w][g][k0 + t4];
            const uint32_t a1 = sm.Pb[w][g + 8][k0 + t4];
            const uint32_t a2 = sm.Pb[w][g][k0 + t4 + 4];
            const uint32_t a3 = sm.Pb[w][g + 8][k0 + t4 + 4];
#pragma unroll
            for (int nb = 0; nb < 8; nb++) {
                const int dc = nb * 8 + g;
                const uint32_t b0 = sm.Vb[cur][k0 + t4][dc];
                const uint32_t b1 = sm.Vb[cur][k0 + t4 + 4][dc];
                mma_tf32(obuf[nb], a0, a1, a2, a3, b0, b1);
            }
        }
        __syncwarp();
    }

    // ---- epilogue (tf32-rounded: consumed by tf32 proj GEMM) ----
    const float inv_lo = 1.0f / l_lo;
    const float inv_hi = 1.0f / l_hi;
    float* o_lo = out + ((size_t)b * SEQ + q0 + qr + g) * DIM + h * HDIM;
    float* o_hi = out + ((size_t)b * SEQ + q0 + qr + 8 + g) * DIM + h * HDIM;
#pragma unroll
    for (int nb = 0; nb < 8; nb++) {
        const int c = nb * 8 + 2 * t4;
        *reinterpret_cast<float2*>(o_lo + c) =
            make_float2(tf32r(obuf[nb][0] * inv_lo), tf32r(obuf[nb][1] * inv_lo));
        *reinterpret_cast<float2*>(o_hi + c) =
            make_float2(tf32r(obuf[nb][2] * inv_hi), tf32r(obuf[nb][3] * inv_hi));
    }
}

// ---------------------------------------------------------------------------
extern "C" void kernel_launch(void* const* d_in, const int* in_sizes, int n_in,
                              void* d_out, int out_size)
{
    const float* x      = (const float*)d_in[0];
    const float* w_qkv  = (const float*)d_in[1];
    const float* b_qkv  = (const float*)d_in[2];
    const float* w_proj = (const float*)d_in[3];
    const float* b_proj = (const float*)d_in[4];
    float* out = (float*)d_out;

    float *qkv, *att, *xr, *wqkvT, *wprojT;
    cudaGetSymbolAddress((void**)&qkv, g_qkv);
    cudaGetSymbolAddress((void**)&att, g_att);
    cudaGetSymbolAddress((void**)&xr, g_xr);
    cudaGetSymbolAddress((void**)&wqkvT, g_wqkvT);
    cudaGetSymbolAddress((void**)&wprojT, g_wprojT);

    cudaFuncSetAttribute(attn_kernel, cudaFuncAttributeMaxDynamicSharedMemorySize,
                         (int)sizeof(AttnSmem));
    cudaFuncSetAttribute(gemm_mma_kernel<true>,
                         cudaFuncAttributeMaxDynamicSharedMemorySize, GEMM_SMEM_BYTES);
    cudaFuncSetAttribute(gemm_mma_kernel<false>,
                         cudaFuncAttributeMaxDynamicSharedMemorySize, GEMM_SMEM_BYTES);

    // 0) Producers: round once (numerically identical to consumer-side cvt)
    cvt_tf32_kernel<<<(ROWS * DIM / 4 + 255) / 256, 256>>>(x, xr, ROWS * DIM / 4);
    transpose_kernel<<<dim3(QKV_COLS / 32, DIM / 32), dim3(32, 8)>>>(
        w_qkv, wqkvT, DIM, QKV_COLS);
    transpose_kernel<<<dim3(DIM / 32, DIM / 32), dim3(32, 8)>>>(
        w_proj, wprojT, DIM, DIM);

    // 1) QKV projection (rounds output for attention)
    gemm_mma_kernel<true><<<dim3(QKV_COLS / 128, ROWS / 128), 256, GEMM_SMEM_BYTES>>>(
        xr, wqkvT, b_qkv, qkv, ROWS, QKV_COLS, DIM);

    // 2) Multi-head attention
    attn_kernel<<<dim3(SEQ / 128, BATCH * NHEAD), 256, sizeof(AttnSmem)>>>(qkv, att);

    // 3) Output projection (full fp32 output)
    gemm_mma_kernel<false><<<dim3(DIM / 128, ROWS / 128), 256, GEMM_SMEM_BYTES>>>(
        att, wprojT, b_proj, out, ROWS, DIM, DIM);
}

// round 8
// speedup vs baseline: 4.4199x; 1.0561x over previous
#include <cuda_runtime.h>
#include <cuda_bf16.h>
#include <math.h>
#include <stdint.h>

// Problem constants
#define BATCH 2
#define SEQ 2048
#define DIM 1024
#define NHEAD 16
#define HDIM 64
#define QKV_COLS (3 * DIM)          // 3072
#define ROWS (BATCH * SEQ)          // 4096
#define SCALE 0.03125f              // 1024^-0.5

// Scratch in device globals (no allocation allowed)
__device__ float g_qkv[ROWS * QKV_COLS];       // [4096, 3072] (tf32-rounded)
__device__ float g_att[ROWS * DIM];            // [4096, 1024] (tf32-rounded)
__device__ float g_xr[ROWS * DIM];             // x, tf32-rounded
__device__ float g_wqkvT[QKV_COLS * DIM];      // [3072, 1024] (tf32-rounded)
__device__ float g_wprojT[DIM * DIM];          // [1024, 1024] (tf32-rounded)

// ---------------------------------------------------------------------------
// Helpers
// ---------------------------------------------------------------------------
__device__ __forceinline__ uint32_t f2tf32(float f) {
    uint32_t r;
    asm("cvt.rna.tf32.f32 %0, %1;" : "=r"(r) : "f"(f));
    return r;
}
__device__ __forceinline__ float tf32r(float f) {
    return __uint_as_float(f2tf32(f));
}

// k-slot note: we feed smem positions (2*t4, 2*t4+1) into fragment slots
// (k=t4, k=t4+4) on BOTH A and B sides. The MMA sums a_slot*b_slot over all
// 8 slots; since both sides use the same position->slot bijection, the result
// is the same dot product — but each thread's two k-values are now adjacent,
// enabling 64-bit shared loads.
__device__ __forceinline__ void mma_tf32(float c[4],
    uint32_t a0, uint32_t a1, uint32_t a2, uint32_t a3,
    uint32_t b0, uint32_t b1)
{
    asm volatile(
        "mma.sync.aligned.m16n8k8.row.col.f32.tf32.tf32.f32 "
        "{%0,%1,%2,%3}, {%4,%5,%6,%7}, {%8,%9}, {%0,%1,%2,%3};"
        : "+f"(c[0]), "+f"(c[1]), "+f"(c[2]), "+f"(c[3])
        : "r"(a0), "r"(a1), "r"(a2), "r"(a3), "r"(b0), "r"(b1));
}

__device__ __forceinline__ uint32_t smem_u32(const void* p) {
    uint32_t a;
    asm("{ .reg .u64 t; cvta.to.shared.u64 t, %1; cvt.u32.u64 %0, t; }"
        : "=r"(a) : "l"(p));
    return a;
}

__device__ __forceinline__ void cp_async16(uint32_t dst, const void* src) {
    asm volatile("cp.async.cg.shared.global [%0], [%1], 16;"
                 :: "r"(dst), "l"(src));
}
#define CP_COMMIT() asm volatile("cp.async.commit_group;" ::: "memory")
#define CP_WAIT0()  asm volatile("cp.async.wait_group 0;" ::: "memory")

// ---------------------------------------------------------------------------
// Elementwise tf32 rounding
// ---------------------------------------------------------------------------
__global__ __launch_bounds__(256) void cvt_tf32_kernel(
    const float* __restrict__ in, float* __restrict__ out, int n4)
{
    const int i = blockIdx.x * 256 + threadIdx.x;
    if (i < n4) {
        float4 v = reinterpret_cast<const float4*>(in)[i];
        v.x = tf32r(v.x); v.y = tf32r(v.y);
        v.z = tf32r(v.z); v.w = tf32r(v.w);
        reinterpret_cast<float4*>(out)[i] = v;
    }
}

// ---------------------------------------------------------------------------
// Transpose + tf32 round: out[n*K + k] = tf32(in[k*N + n]).
// ---------------------------------------------------------------------------
__global__ __launch_bounds__(256) void transpose_kernel(
    const float* __restrict__ in, float* __restrict__ out, int K, int N)
{
    __shared__ float tile[32][33];
    const int n0 = blockIdx.x * 32;
    const int k0 = blockIdx.y * 32;
    const int tx = threadIdx.x, ty = threadIdx.y;
#pragma unroll
    for (int i = 0; i < 32; i += 8)
        tile[ty + i][tx] = tf32r(in[(size_t)(k0 + ty + i) * N + n0 + tx]);
    __syncthreads();
#pragma unroll
    for (int i = 0; i < 32; i += 8)
        out[(size_t)(n0 + ty + i) * K + k0 + tx] = tile[tx][ty + i];
}

// ---------------------------------------------------------------------------
// mma.sync tf32 GEMM: C[M,N] = A[M,K] @ Bt[N,K]^T + bias[N]
// Pre-rounded inputs. 128x128 tile, BK=32, cp.async double-buffered,
// 256 threads, 2 CTAs/SM, 1 barrier per chunk, LDS.64 fragments.
// ---------------------------------------------------------------------------
#define BK 32
#define GPAD 40                         // mod 32 == 8 -> conflict-free LDS.64
#define GSTG (128 * GPAD)
#define GEMM_SMEM_BYTES (4 * GSTG * 4)  // 2 stages x (A+B) = 163840/2CTA ok

template <bool ROUND_OUT>
__global__ __launch_bounds__(256, 2) void gemm_mma_kernel(
    const float* __restrict__ A, const float* __restrict__ Bt,
    const float* __restrict__ bias, float* __restrict__ C,
    int M, int N, int K)
{
    extern __shared__ float dsm[];
    float* sA = dsm;
    float* sB = dsm + 2 * GSTG;
    const uint32_t sAb = smem_u32(sA);
    const uint32_t sBb = smem_u32(sB);

    const int t    = threadIdx.x;
    const int lane = t & 31;
    const int w    = t >> 5;
    const int wm   = w >> 2;
    const int wn   = w & 3;
    const int g    = lane >> 2;
    const int t4   = lane & 3;
    const int row0 = blockIdx.y * 128;
    const int col0 = blockIdx.x * 128;

    float acc[4][4][4];
#pragma unroll
    for (int i = 0; i < 4; i++)
#pragma unroll
        for (int j = 0; j < 4; j++)
#pragma unroll
            for (int q = 0; q < 4; q++) acc[i][j][q] = 0.0f;

    const int nchunk = K / BK;

    auto load_stage = [&](int stg, int ck) {
        const int k0 = ck * BK;
#pragma unroll
        for (int i = 0; i < 4; i++) {
            const int id = t + i * 256;
            const int r  = id >> 3;
            const int c  = id & 7;
            cp_async16(sAb + (uint32_t)((stg * GSTG + r * GPAD + c * 4) * 4),
                       A + (size_t)(row0 + r) * K + k0 + c * 4);
            cp_async16(sBb + (uint32_t)((stg * GSTG + r * GPAD + c * 4) * 4),
                       Bt + (size_t)(col0 + r) * K + k0 + c * 4);
        }
    };

    load_stage(0, 0);
    CP_COMMIT();

    for (int ck = 0; ck < nchunk; ck++) {
        CP_WAIT0();            // stage ck landed (only pending group)
        __syncthreads();       // visible to all; all done reading other buf
        if (ck + 1 < nchunk) {
            load_stage((ck + 1) & 1, ck + 1);
            CP_COMMIT();
        }

        const uint32_t* cA =
            reinterpret_cast<const uint32_t*>(sA + (ck & 1) * GSTG);
        const uint32_t* cB =
            reinterpret_cast<const uint32_t*>(sB + (ck & 1) * GSTG);

#pragma unroll
        for (int ks = 0; ks < 4; ks++) {
            const int k0 = ks * 8 + 2 * t4;
            uint2 alo[4], ahi[4];
#pragma unroll
            for (int mb = 0; mb < 4; mb++) {
                const int r = wm * 64 + mb * 16 + g;
                alo[mb] = *reinterpret_cast<const uint2*>(&cA[r * GPAD + k0]);
                ahi[mb] = *reinterpret_cast<const uint2*>(&cA[(r + 8) * GPAD + k0]);
            }
            uint2 bv[4];
#pragma unroll
            for (int nb = 0; nb < 4; nb++) {
                const int c = wn * 32 + nb * 8 + g;
                bv[nb] = *reinterpret_cast<const uint2*>(&cB[c * GPAD + k0]);
            }
#pragma unroll
            for (int mb = 0; mb < 4; mb++)
#pragma unroll
                for (int nb = 0; nb < 4; nb++)
                    mma_tf32(acc[mb][nb], alo[mb].x, ahi[mb].x, alo[mb].y,
                             ahi[mb].y, bv[nb].x, bv[nb].y);
        }
        __syncthreads();   // all reads of buf ck&1 done before next overwrite
    }

#pragma unroll
    for (int mb = 0; mb < 4; mb++) {
        const int r = row0 + wm * 64 + mb * 16 + g;
#pragma unroll
        for (int nb = 0; nb < 4; nb++) {
            const int c = col0 + wn * 32 + nb * 8 + 2 * t4;
            const float b0 = bias[c], b1 = bias[c + 1];
            float2 v0, v1;
            if (ROUND_OUT) {
                v0 = make_float2(tf32r(acc[mb][nb][0] + b0),
                                 tf32r(acc[mb][nb][1] + b1));
                v1 = make_float2(tf32r(acc[mb][nb][2] + b0),
                                 tf32r(acc[mb][nb][3] + b1));
            } else {
                v0 = make_float2(acc[mb][nb][0] + b0, acc[mb][nb][1] + b1);
                v1 = make_float2(acc[mb][nb][2] + b0, acc[mb][nb][3] + b1);
            }
            *reinterpret_cast<float2*>(C + (size_t)r * N + c) = v0;
            *reinterpret_cast<float2*>(C + (size_t)(r + 8) * N + c) = v1;
        }
    }
}

// ---------------------------------------------------------------------------
// Flash-attention v5: cp.async double-buffered K/V, LDS.64 K/P fragments
// (k-slot pairing), V rows re-paired to (2t4, 2t4+1). 2 CTAs/SM.
// 8 warps x 16 query rows. grid = (S/128, B*H).
// ---------------------------------------------------------------------------
#define KB_STRIDE 72    // mod 32 == 8 -> conflict-free LDS.64
#define VB_STRIDE 68    // row-based loads conflict-free at mod 32 == 4
#define PB_STRIDE 72

struct AttnSmem {
    uint32_t Kb[2][64][KB_STRIDE];
    uint32_t Vb[2][64][VB_STRIDE];
    uint32_t Pb[8][16][PB_STRIDE];
};

__global__ __launch_bounds__(256, 2) void attn_kernel(
    const float* __restrict__ qkv, float* __restrict__ out)
{
    extern __shared__ char smem_raw[];
    AttnSmem& sm = *reinterpret_cast<AttnSmem*>(smem_raw);

    const int t    = threadIdx.x;
    const int lane = t & 31;
    const int w    = t >> 5;
    const int g    = lane >> 2;
    const int t4   = lane & 3;
    const int qr   = w * 16;

    const int qt = blockIdx.x;
    const int bh = blockIdx.y;
    const int b  = bh >> 4;
    const int h  = bh & 15;

    const size_t base = (size_t)b * SEQ * QKV_COLS + (size_t)h * (3 * HDIM);
    const int q0 = qt * 128;

    // cp.async staging: 64 rows x 16 float4 per tensor; 4 threads/row,
    // 4 float4 per tensor per thread.
    const int sr  = t >> 2;
    const int sc4 = (t & 3) * 4;

    const uint32_t kbase = smem_u32(&sm.Kb[0][sr][sc4]);
    const uint32_t vbase = smem_u32(&sm.Vb[0][sr][sc4]);
    const uint32_t kbufstride = (uint32_t)(64 * KB_STRIDE * 4);
    const uint32_t vbufstride = (uint32_t)(64 * VB_STRIDE * 4);

    auto prefetch = [&](int kt, int bufi) {
        const float* src = qkv + base + (size_t)(kt * 64 + sr) * QKV_COLS;
        const uint32_t kd = kbase + bufi * kbufstride;
        const uint32_t vd = vbase + bufi * vbufstride;
#pragma unroll
        for (int i = 0; i < 4; i++) {
            cp_async16(kd + i * 64, src + 64 + sc4 + i * 16);
            cp_async16(vd + i * 64, src + 128 + sc4 + i * 16);
        }
        CP_COMMIT();
    };

    // ---- Q fragments (pre-rounded; SCALE=2^-5 exact); slots get positions
    //      (2t4, 2t4+1) to match the K-side pairing ----
    uint32_t Qf[8][4];
    {
        const size_t rlo = base + (size_t)(q0 + qr + g) * QKV_COLS;
        const size_t rhi = base + (size_t)(q0 + qr + 8 + g) * QKV_COLS;
#pragma unroll
        for (int ks = 0; ks < 8; ks++) {
            const int k0 = ks * 8 + 2 * t4;
            Qf[ks][0] = __float_as_uint(SCALE * qkv[rlo + k0]);
            Qf[ks][1] = __float_as_uint(SCALE * qkv[rhi + k0]);
            Qf[ks][2] = __float_as_uint(SCALE * qkv[rlo + k0 + 1]);
            Qf[ks][3] = __float_as_uint(SCALE * qkv[rhi + k0 + 1]);
        }
    }

    float obuf[8][4];
#pragma unroll
    for (int nb = 0; nb < 8; nb++)
#pragma unroll
        for (int q = 0; q < 4; q++) obuf[nb][q] = 0.0f;

    float m_lo = -INFINITY, m_hi = -INFINITY;
    float l_lo = 0.0f, l_hi = 0.0f;

    prefetch(0, 0);

    const int NT = SEQ / 64;
    for (int kt = 0; kt < NT; kt++) {
        const int cur = kt & 1;
        CP_WAIT0();
        __syncthreads();
        if (kt + 1 < NT) prefetch(kt + 1, cur ^ 1);

        // ---- S = Q @ K^T (LDS.64 K fragments) ----
        float sacc[8][4];
#pragma unroll
        for (int nb = 0; nb < 8; nb++)
#pragma unroll
            for (int q = 0; q < 4; q++) sacc[nb][q] = 0.0f;

#pragma unroll
        for (int ks = 0; ks < 8; ks++) {
            const int k0 = ks * 8 + 2 * t4;
#pragma unroll
            for (int nb = 0; nb < 8; nb++) {
                const int kc = nb * 8 + g;
                const uint2 kv =
                    *reinterpret_cast<const uint2*>(&sm.Kb[cur][kc][k0]);
                mma_tf32(sacc[nb], Qf[ks][0], Qf[ks][1], Qf[ks][2], Qf[ks][3],
                         kv.x, kv.y);
            }
        }

        // ---- warp-private online softmax ----
        float mx_lo = -INFINITY, mx_hi = -INFINITY;
#pragma unroll
        for (int nb = 0; nb < 8; nb++) {
            mx_lo = fmaxf(mx_lo, fmaxf(sacc[nb][0], sacc[nb][1]));
            mx_hi = fmaxf(mx_hi, fmaxf(sacc[nb][2], sacc[nb][3]));
        }
        mx_lo = fmaxf(mx_lo, __shfl_xor_sync(0xffffffffu, mx_lo, 1));
        mx_lo = fmaxf(mx_lo, __shfl_xor_sync(0xffffffffu, mx_lo, 2));
        mx_hi = fmaxf(mx_hi, __shfl_xor_sync(0xffffffffu, mx_hi, 1));
        mx_hi = fmaxf(mx_hi, __shfl_xor_sync(0xffffffffu, mx_hi, 2));

        const float mn_lo = fmaxf(m_lo, mx_lo);
        const float mn_hi = fmaxf(m_hi, mx_hi);
        const float alpha_lo = __expf(m_lo - mn_lo);
        const float alpha_hi = __expf(m_hi - mn_hi);
        m_lo = mn_lo; m_hi = mn_hi;

        float sum_lo = 0.0f, sum_hi = 0.0f;
#pragma unroll
        for (int nb = 0; nb < 8; nb++) {
            const int c = nb * 8 + 2 * t4;
            const float p0 = __expf(sacc[nb][0] - mn_lo);
            const float p1 = __expf(sacc[nb][1] - mn_lo);
            const float p2 = __expf(sacc[nb][2] - mn_hi);
            const float p3 = __expf(sacc[nb][3] - mn_hi);
            sum_lo += p0 + p1;
            sum_hi += p2 + p3;
            uint2 plo, phi;
            plo.x = f2tf32(p0); plo.y = f2tf32(p1);
            phi.x = f2tf32(p2); phi.y = f2tf32(p3);
            *reinterpret_cast<uint2*>(&sm.Pb[w][g][c]) = plo;
            *reinterpret_cast<uint2*>(&sm.Pb[w][g + 8][c]) = phi;
        }
        sum_lo += __shfl_xor_sync(0xffffffffu, sum_lo, 1);
        sum_lo += __shfl_xor_sync(0xffffffffu, sum_lo, 2);
        sum_hi += __shfl_xor_sync(0xffffffffu, sum_hi, 1);
        sum_hi += __shfl_xor_sync(0xffffffffu, sum_hi, 2);
        l_lo = l_lo * alpha_lo + sum_lo;
        l_hi = l_hi * alpha_hi + sum_hi;

        __syncwarp();

#pragma unroll
        for (int nb = 0; nb < 8; nb++) {
            obuf[nb][0] *= alpha_lo; obuf[nb][1] *= alpha_lo;
            obuf[nb][2] *= alpha_hi; obuf[nb][3] *= alpha_hi;
        }

        // ---- O += P @ V (LDS.64 P fragments; V rows (2t4, 2t4+1)) ----
#pragma unroll
        for (int ks = 0; ks < 8; ks++) {
            const int k0 = ks * 8 + 2 * t4;
            const uint2 plo =
                *reinterpret_cast<const uint2*>(&sm.Pb[w][g][k0]);
            const uint2 phi =
                *reinterpret_cast<const uint2*>(&sm.Pb[w][g + 8][k0]);
#pragma unroll
            for (int nb = 0; nb < 8; nb++) {
                const int dc = nb * 8 + g;
                const uint32_t b0 = sm.Vb[cur][k0][dc];
                const uint32_t b1 = sm.Vb[cur][k0 + 1][dc];
                mma_tf32(obuf[nb], plo.x, phi.x, plo.y, phi.y, b0, b1);
            }
        }
        __syncwarp();
    }

    // ---- epilogue (tf32-rounded: consumed by tf32 proj GEMM) ----
    const float inv_lo = 1.0f / l_lo;
    const float inv_hi = 1.0f / l_hi;
    float* o_lo = out + ((size_t)b * SEQ + q0 + qr + g) * DIM + h * HDIM;
    float* o_hi = out + ((size_t)b * SEQ + q0 + qr + 8 + g) * DIM + h * HDIM;
#pragma unroll
    for (int nb = 0; nb < 8; nb++) {
        const int c = nb * 8 + 2 * t4;
        *reinterpret_cast<float2*>(o_lo + c) =
            make_float2(tf32r(obuf[nb][0] * inv_lo), tf32r(obuf[nb][1] * inv_lo));
        *reinterpret_cast<float2*>(o_hi + c) =
            make_float2(tf32r(obuf[nb][2] * inv_hi), tf32r(obuf[nb][3] * inv_hi));
    }
}

// ---------------------------------------------------------------------------
extern "C" void kernel_launch(void* const* d_in, const int* in_sizes, int n_in,
                              void* d_out, int out_size)
{
    const float* x      = (const float*)d_in[0];
    const float* w_qkv  = (const float*)d_in[1];
    const float* b_qkv  = (const float*)d_in[2];
    const float* w_proj = (const float*)d_in[3];
    const float* b_proj = (const float*)d_in[4];
    float* out = (float*)d_out;

    float *qkv, *att, *xr, *wqkvT, *wprojT;
    cudaGetSymbolAddress((void**)&qkv, g_qkv);
    cudaGetSymbolAddress((void**)&att, g_att);
    cudaGetSymbolAddress((void**)&xr, g_xr);
    cudaGetSymbolAddress((void**)&wqkvT, g_wqkvT);
    cudaGetSymbolAddress((void**)&wprojT, g_wprojT);

    cudaFuncSetAttribute(attn_kernel, cudaFuncAttributeMaxDynamicSharedMemorySize,
                         (int)sizeof(AttnSmem));
    cudaFuncSetAttribute(gemm_mma_kernel<true>,
                         cudaFuncAttributeMaxDynamicSharedMemorySize, GEMM_SMEM_BYTES);
    cudaFuncSetAttribute(gemm_mma_kernel<false>,
                         cudaFuncAttributeMaxDynamicSharedMemorySize, GEMM_SMEM_BYTES);

    // 0) Producers: round once (numerically identical to consumer-side cvt)
    cvt_tf32_kernel<<<(ROWS * DIM / 4 + 255) / 256, 256>>>(x, xr, ROWS * DIM / 4);
    transpose_kernel<<<dim3(QKV_COLS / 32, DIM / 32), dim3(32, 8)>>>(
        w_qkv, wqkvT, DIM, QKV_COLS);
    transpose_kernel<<<dim3(DIM / 32, DIM / 32), dim3(32, 8)>>>(
        w_proj, wprojT, DIM, DIM);

    // 1) QKV projection (rounds output for attention)
    gemm_mma_kernel<true><<<dim3(QKV_COLS / 128, ROWS / 128), 256, GEMM_SMEM_BYTES>>>(
        xr, wqkvT, b_qkv, qkv, ROWS, QKV_COLS, DIM);

    // 2) Multi-head attention
    attn_kernel<<<dim3(SEQ / 128, BATCH * NHEAD), 256, sizeof(AttnSmem)>>>(qkv, att);

    // 3) Output projection (full fp32 output)
    gemm_mma_kernel<false><<<dim3(DIM / 128, ROWS / 128), 256, GEMM_SMEM_BYTES>>>(
        att, wprojT, b_proj, out, ROWS, DIM, DIM);
}

// round 9
// speedup vs baseline: 4.7512x; 1.0750x over previous
#include <cuda_runtime.h>
#include <cuda_bf16.h>
#include <math.h>
#include <stdint.h>

// Problem constants
#define BATCH 2
#define SEQ 2048
#define DIM 1024
#define NHEAD 16
#define HDIM 64
#define QKV_COLS (3 * DIM)          // 3072
#define ROWS (BATCH * SEQ)          // 4096
#define SCALE 0.03125f              // 1024^-0.5

// Scratch in device globals (no allocation allowed)
__device__ float g_qkv[ROWS * QKV_COLS];       // [4096, 3072] (tf32-rounded)
__device__ float g_att[ROWS * DIM];            // [4096, 1024] (tf32-rounded)
__device__ float g_xr[ROWS * DIM];             // x, tf32-rounded
__device__ float g_wqkvT[QKV_COLS * DIM];      // [3072, 1024] (tf32-rounded)
__device__ float g_wprojT[DIM * DIM];          // [1024, 1024] (tf32-rounded)

// ---------------------------------------------------------------------------
// Helpers
// ---------------------------------------------------------------------------
__device__ __forceinline__ uint32_t f2tf32(float f) {
    uint32_t r;
    asm("cvt.rna.tf32.f32 %0, %1;" : "=r"(r) : "f"(f));
    return r;
}
__device__ __forceinline__ float tf32r(float f) {
    return __uint_as_float(f2tf32(f));
}

// k-slot note: smem positions (2*t4, 2*t4+1) feed fragment slots (t4, t4+4)
// on BOTH A and B sides — same bijection both sides => identical dot product,
// but each thread's two k-values are adjacent (LDS.64).
__device__ __forceinline__ void mma_tf32(float c[4],
    uint32_t a0, uint32_t a1, uint32_t a2, uint32_t a3,
    uint32_t b0, uint32_t b1)
{
    asm volatile(
        "mma.sync.aligned.m16n8k8.row.col.f32.tf32.tf32.f32 "
        "{%0,%1,%2,%3}, {%4,%5,%6,%7}, {%8,%9}, {%0,%1,%2,%3};"
        : "+f"(c[0]), "+f"(c[1]), "+f"(c[2]), "+f"(c[3])
        : "r"(a0), "r"(a1), "r"(a2), "r"(a3), "r"(b0), "r"(b1));
}

__device__ __forceinline__ uint32_t smem_u32(const void* p) {
    uint32_t a;
    asm("{ .reg .u64 t; cvta.to.shared.u64 t, %1; cvt.u32.u64 %0, t; }"
        : "=r"(a) : "l"(p));
    return a;
}

__device__ __forceinline__ void cp_async16(uint32_t dst, const void* src) {
    asm volatile("cp.async.cg.shared.global [%0], [%1], 16;"
                 :: "r"(dst), "l"(src));
}
#define CP_COMMIT() asm volatile("cp.async.commit_group;" ::: "memory")
#define CP_WAIT0()  asm volatile("cp.async.wait_group 0;" ::: "memory")

// ---------------------------------------------------------------------------
// Elementwise tf32 rounding
// ---------------------------------------------------------------------------
__global__ __launch_bounds__(256) void cvt_tf32_kernel(
    const float* __restrict__ in, float* __restrict__ out, int n4)
{
    const int i = blockIdx.x * 256 + threadIdx.x;
    if (i < n4) {
        float4 v = reinterpret_cast<const float4*>(in)[i];
        v.x = tf32r(v.x); v.y = tf32r(v.y);
        v.z = tf32r(v.z); v.w = tf32r(v.w);
        reinterpret_cast<float4*>(out)[i] = v;
    }
}

// ---------------------------------------------------------------------------
// Transpose + tf32 round: out[n*K + k] = tf32(in[k*N + n]).
// ---------------------------------------------------------------------------
__global__ __launch_bounds__(256) void transpose_kernel(
    const float* __restrict__ in, float* __restrict__ out, int K, int N)
{
    __shared__ float tile[32][33];
    const int n0 = blockIdx.x * 32;
    const int k0 = blockIdx.y * 32;
    const int tx = threadIdx.x, ty = threadIdx.y;
#pragma unroll
    for (int i = 0; i < 32; i += 8)
        tile[ty + i][tx] = tf32r(in[(size_t)(k0 + ty + i) * N + n0 + tx]);
    __syncthreads();
#pragma unroll
    for (int i = 0; i < 32; i += 8)
        out[(size_t)(n0 + ty + i) * K + k0 + tx] = tile[tx][ty + i];
}

// ---------------------------------------------------------------------------
// mma.sync tf32 GEMM: C[M,N] = A[M,K] @ Bt[N,K]^T + bias[N]
// Pre-rounded inputs. 128x128 tile, BK=32, cp.async double-buffered,
// 256 threads, 2 CTAs/SM, ONE barrier per chunk, LDS.64 fragments.
// ---------------------------------------------------------------------------
#define BK 32
#define GPAD 40
#define GSTG (128 * GPAD)
#define GEMM_SMEM_BYTES (4 * GSTG * 4)

template <bool ROUND_OUT>
__global__ __launch_bounds__(256, 2) void gemm_mma_kernel(
    const float* __restrict__ A, const float* __restrict__ Bt,
    const float* __restrict__ bias, float* __restrict__ C,
    int M, int N, int K)
{
    extern __shared__ float dsm[];
    float* sA = dsm;
    float* sB = dsm + 2 * GSTG;
    const uint32_t sAb = smem_u32(sA);
    const uint32_t sBb = smem_u32(sB);

    const int t    = threadIdx.x;
    const int lane = t & 31;
    const int w    = t >> 5;
    const int wm   = w >> 2;
    const int wn   = w & 3;
    const int g    = lane >> 2;
    const int t4   = lane & 3;
    const int row0 = blockIdx.y * 128;
    const int col0 = blockIdx.x * 128;

    float acc[4][4][4];
#pragma unroll
    for (int i = 0; i < 4; i++)
#pragma unroll
        for (int j = 0; j < 4; j++)
#pragma unroll
            for (int q = 0; q < 4; q++) acc[i][j][q] = 0.0f;

    const int nchunk = K / BK;

    auto load_stage = [&](int stg, int ck) {
        const int k0 = ck * BK;
#pragma unroll
        for (int i = 0; i < 4; i++) {
            const int id = t + i * 256;
            const int r  = id >> 3;
            const int c  = id & 7;
            cp_async16(sAb + (uint32_t)((stg * GSTG + r * GPAD + c * 4) * 4),
                       A + (size_t)(row0 + r) * K + k0 + c * 4);
            cp_async16(sBb + (uint32_t)((stg * GSTG + r * GPAD + c * 4) * 4),
                       Bt + (size_t)(col0 + r) * K + k0 + c * 4);
        }
    };

    load_stage(0, 0);
    CP_COMMIT();

    for (int ck = 0; ck < nchunk; ck++) {
        CP_WAIT0();            // stage ck landed
        __syncthreads();       // all warps finished reading the other buffer
        if (ck + 1 < nchunk) {
            load_stage((ck + 1) & 1, ck + 1);   // writes buf != cur: safe
            CP_COMMIT();
        }

        const uint32_t* cA =
            reinterpret_cast<const uint32_t*>(sA + (ck & 1) * GSTG);
        const uint32_t* cB =
            reinterpret_cast<const uint32_t*>(sB + (ck & 1) * GSTG);

#pragma unroll
        for (int ks = 0; ks < 4; ks++) {
            const int k0 = ks * 8 + 2 * t4;
            uint2 alo[4], ahi[4];
#pragma unroll
            for (int mb = 0; mb < 4; mb++) {
                const int r = wm * 64 + mb * 16 + g;
                alo[mb] = *reinterpret_cast<const uint2*>(&cA[r * GPAD + k0]);
                ahi[mb] = *reinterpret_cast<const uint2*>(&cA[(r + 8) * GPAD + k0]);
            }
            uint2 bv[4];
#pragma unroll
            for (int nb = 0; nb < 4; nb++) {
                const int c = wn * 32 + nb * 8 + g;
                bv[nb] = *reinterpret_cast<const uint2*>(&cB[c * GPAD + k0]);
            }
#pragma unroll
            for (int mb = 0; mb < 4; mb++)
#pragma unroll
                for (int nb = 0; nb < 4; nb++)
                    mma_tf32(acc[mb][nb], alo[mb].x, ahi[mb].x, alo[mb].y,
                             ahi[mb].y, bv[nb].x, bv[nb].y);
        }
        // no bottom barrier: next iteration's top __syncthreads() orders
        // all reads of this buffer before the prefetch that overwrites it
    }

#pragma unroll
    for (int mb = 0; mb < 4; mb++) {
        const int r = row0 + wm * 64 + mb * 16 + g;
#pragma unroll
        for (int nb = 0; nb < 4; nb++) {
            const int c = col0 + wn * 32 + nb * 8 + 2 * t4;
            const float b0 = bias[c], b1 = bias[c + 1];
            float2 v0, v1;
            if (ROUND_OUT) {
                v0 = make_float2(tf32r(acc[mb][nb][0] + b0),
                                 tf32r(acc[mb][nb][1] + b1));
                v1 = make_float2(tf32r(acc[mb][nb][2] + b0),
                                 tf32r(acc[mb][nb][3] + b1));
            } else {
                v0 = make_float2(acc[mb][nb][0] + b0, acc[mb][nb][1] + b1);
                v1 = make_float2(acc[mb][nb][2] + b0, acc[mb][nb][3] + b1);
            }
            *reinterpret_cast<float2*>(C + (size_t)r * N + c) = v0;
            *reinterpret_cast<float2*>(C + (size_t)(r + 8) * N + c) = v1;
        }
    }
}

// ---------------------------------------------------------------------------
// Flash-attention v6: P stays in registers — the C-fragment layout of sacc
// under k-slot pairing IS the A-fragment layout for P@V, so exp() + tf32
// rounding happen in-place and PV consumes sacc directly. No P smem, no
// syncwarp. cp.async double-buffered K/V, 2 CTAs/SM, 8 warps x 16 q-rows.
// grid = (S/128, B*H).
// ---------------------------------------------------------------------------
#define KB_STRIDE 72    // mod 32 == 8 -> conflict-free LDS.64
#define VB_STRIDE 68    // mod 32 == 4 -> conflict-free LDS.32 pattern

struct AttnSmem {
    uint32_t Kb[2][64][KB_STRIDE];
    uint32_t Vb[2][64][VB_STRIDE];
};

__global__ __launch_bounds__(256, 2) void attn_kernel(
    const float* __restrict__ qkv, float* __restrict__ out)
{
    extern __shared__ char smem_raw[];
    AttnSmem& sm = *reinterpret_cast<AttnSmem*>(smem_raw);

    const int t    = threadIdx.x;
    const int lane = t & 31;
    const int w    = t >> 5;
    const int g    = lane >> 2;
    const int t4   = lane & 3;
    const int qr   = w * 16;

    const int qt = blockIdx.x;
    const int bh = blockIdx.y;
    const int b  = bh >> 4;
    const int h  = bh & 15;

    const size_t base = (size_t)b * SEQ * QKV_COLS + (size_t)h * (3 * HDIM);
    const int q0 = qt * 128;

    // cp.async staging: 64 rows x 16 float4 per tensor; 4 threads/row.
    const int sr  = t >> 2;
    const int sc4 = (t & 3) * 4;

    const uint32_t kbase = smem_u32(&sm.Kb[0][sr][sc4]);
    const uint32_t vbase = smem_u32(&sm.Vb[0][sr][sc4]);
    const uint32_t kbufstride = (uint32_t)(64 * KB_STRIDE * 4);
    const uint32_t vbufstride = (uint32_t)(64 * VB_STRIDE * 4);

    auto prefetch = [&](int kt, int bufi) {
        const float* src = qkv + base + (size_t)(kt * 64 + sr) * QKV_COLS;
        const uint32_t kd = kbase + bufi * kbufstride;
        const uint32_t vd = vbase + bufi * vbufstride;
#pragma unroll
        for (int i = 0; i < 4; i++) {
            cp_async16(kd + i * 64, src + 64 + sc4 + i * 16);
            cp_async16(vd + i * 64, src + 128 + sc4 + i * 16);
        }
        CP_COMMIT();
    };

    // ---- Q fragments (pre-rounded; SCALE=2^-5 exact); positions
    //      (2t4, 2t4+1) -> slots (t4, t4+4) ----
    uint32_t Qf[8][4];
    {
        const size_t rlo = base + (size_t)(q0 + qr + g) * QKV_COLS;
        const size_t rhi = base + (size_t)(q0 + qr + 8 + g) * QKV_COLS;
#pragma unroll
        for (int ks = 0; ks < 8; ks++) {
            const int k0 = ks * 8 + 2 * t4;
            Qf[ks][0] = __float_as_uint(SCALE * qkv[rlo + k0]);
            Qf[ks][1] = __float_as_uint(SCALE * qkv[rhi + k0]);
            Qf[ks][2] = __float_as_uint(SCALE * qkv[rlo + k0 + 1]);
            Qf[ks][3] = __float_as_uint(SCALE * qkv[rhi + k0 + 1]);
        }
    }

    float obuf[8][4];
#pragma unroll
    for (int nb = 0; nb < 8; nb++)
#pragma unroll
        for (int q = 0; q < 4; q++) obuf[nb][q] = 0.0f;

    float m_lo = -INFINITY, m_hi = -INFINITY;
    float l_lo = 0.0f, l_hi = 0.0f;

    prefetch(0, 0);

    const int NT = SEQ / 64;
    for (int kt = 0; kt < NT; kt++) {
        const int cur = kt & 1;
        CP_WAIT0();
        __syncthreads();
        if (kt + 1 < NT) prefetch(kt + 1, cur ^ 1);

        // ---- S = Q @ K^T (LDS.64 K fragments) ----
        float sacc[8][4];
#pragma unroll
        for (int nb = 0; nb < 8; nb++)
#pragma unroll
            for (int q = 0; q < 4; q++) sacc[nb][q] = 0.0f;

#pragma unroll
        for (int ks = 0; ks < 8; ks++) {
            const int k0 = ks * 8 + 2 * t4;
#pragma unroll
            for (int nb = 0; nb < 8; nb++) {
                const int kc = nb * 8 + g;
                const uint2 kv =
                    *reinterpret_cast<const uint2*>(&sm.Kb[cur][kc][k0]);
                mma_tf32(sacc[nb], Qf[ks][0], Qf[ks][1], Qf[ks][2], Qf[ks][3],
                         kv.x, kv.y);
            }
        }

        // ---- warp-private online softmax (all in registers) ----
        float mx_lo = -INFINITY, mx_hi = -INFINITY;
#pragma unroll
        for (int nb = 0; nb < 8; nb++) {
            mx_lo = fmaxf(mx_lo, fmaxf(sacc[nb][0], sacc[nb][1]));
            mx_hi = fmaxf(mx_hi, fmaxf(sacc[nb][2], sacc[nb][3]));
        }
        mx_lo = fmaxf(mx_lo, __shfl_xor_sync(0xffffffffu, mx_lo, 1));
        mx_lo = fmaxf(mx_lo, __shfl_xor_sync(0xffffffffu, mx_lo, 2));
        mx_hi = fmaxf(mx_hi, __shfl_xor_sync(0xffffffffu, mx_hi, 1));
        mx_hi = fmaxf(mx_hi, __shfl_xor_sync(0xffffffffu, mx_hi, 2));

        const float mn_lo = fmaxf(m_lo, mx_lo);
        const float mn_hi = fmaxf(m_hi, mx_hi);
        const float alpha_lo = __expf(m_lo - mn_lo);
        const float alpha_hi = __expf(m_hi - mn_hi);
        m_lo = mn_lo; m_hi = mn_hi;

        float sum_lo = 0.0f, sum_hi = 0.0f;
#pragma unroll
        for (int nb = 0; nb < 8; nb++) {
            const float p0 = __expf(sacc[nb][0] - mn_lo);
            const float p1 = __expf(sacc[nb][1] - mn_lo);
            const float p2 = __expf(sacc[nb][2] - mn_hi);
            const float p3 = __expf(sacc[nb][3] - mn_hi);
            sum_lo += p0 + p1;
            sum_hi += p2 + p3;
            // In-place tf32 rounding: sacc becomes the PV A-fragment.
            sacc[nb][0] = __uint_as_float(f2tf32(p0));
            sacc[nb][1] = __uint_as_float(f2tf32(p1));
            sacc[nb][2] = __uint_as_float(f2tf32(p2));
            sacc[nb][3] = __uint_as_float(f2tf32(p3));
        }
        sum_lo += __shfl_xor_sync(0xffffffffu, sum_lo, 1);
        sum_lo += __shfl_xor_sync(0xffffffffu, sum_lo, 2);
        sum_hi += __shfl_xor_sync(0xffffffffu, sum_hi, 1);
        sum_hi += __shfl_xor_sync(0xffffffffu, sum_hi, 2);
        l_lo = l_lo * alpha_lo + sum_lo;
        l_hi = l_hi * alpha_hi + sum_hi;

#pragma unroll
        for (int nb = 0; nb < 8; nb++) {
            obuf[nb][0] *= alpha_lo; obuf[nb][1] *= alpha_lo;
            obuf[nb][2] *= alpha_hi; obuf[nb][3] *= alpha_hi;
        }

        // ---- O += P @ V: A-fragment = sacc[ks] directly ----
        // a0 = P[g][8ks+2t4]   = sacc[ks][0]   (slot t4)
        // a1 = P[g+8][8ks+2t4] = sacc[ks][2]
        // a2 = P[g][8ks+2t4+1] = sacc[ks][1]   (slot t4+4)
        // a3 = P[g+8][8ks+2t4+1] = sacc[ks][3]
#pragma unroll
        for (int ks = 0; ks < 8; ks++) {
            const int k0 = ks * 8 + 2 * t4;
            const uint32_t a0 = __float_as_uint(sacc[ks][0]);
            const uint32_t a1 = __float_as_uint(sacc[ks][2]);
            const uint32_t a2 = __float_as_uint(sacc[ks][1]);
            const uint32_t a3 = __float_as_uint(sacc[ks][3]);
#pragma unroll
            for (int nb = 0; nb < 8; nb++) {
                const int dc = nb * 8 + g;
                const uint32_t b0 = sm.Vb[cur][k0][dc];
                const uint32_t b1 = sm.Vb[cur][k0 + 1][dc];
                mma_tf32(obuf[nb], a0, a1, a2, a3, b0, b1);
            }
        }
    }

    // ---- epilogue (tf32-rounded: consumed by tf32 proj GEMM) ----
    const float inv_lo = 1.0f / l_lo;
    const float inv_hi = 1.0f / l_hi;
    float* o_lo = out + ((size_t)b * SEQ + q0 + qr + g) * DIM + h * HDIM;
    float* o_hi = out + ((size_t)b * SEQ + q0 + qr + 8 + g) * DIM + h * HDIM;
#pragma unroll
    for (int nb = 0; nb < 8; nb++) {
        const int c = nb * 8 + 2 * t4;
        *reinterpret_cast<float2*>(o_lo + c) =
            make_float2(tf32r(obuf[nb][0] * inv_lo), tf32r(obuf[nb][1] * inv_lo));
        *reinterpret_cast<float2*>(o_hi + c) =
            make_float2(tf32r(obuf[nb][2] * inv_hi), tf32r(obuf[nb][3] * inv_hi));
    }
}

// ---------------------------------------------------------------------------
extern "C" void kernel_launch(void* const* d_in, const int* in_sizes, int n_in,
                              void* d_out, int out_size)
{
    const float* x      = (const float*)d_in[0];
    const float* w_qkv  = (const float*)d_in[1];
    const float* b_qkv  = (const float*)d_in[2];
    const float* w_proj = (const float*)d_in[3];
    const float* b_proj = (const float*)d_in[4];
    float* out = (float*)d_out;

    float *qkv, *att, *xr, *wqkvT, *wprojT;
    cudaGetSymbolAddress((void**)&qkv, g_qkv);
    cudaGetSymbolAddress((void**)&att, g_att);
    cudaGetSymbolAddress((void**)&xr, g_xr);
    cudaGetSymbolAddress((void**)&wqkvT, g_wqkvT);
    cudaGetSymbolAddress((void**)&wprojT, g_wprojT);

    cudaFuncSetAttribute(attn_kernel, cudaFuncAttributeMaxDynamicSharedMemorySize,
                         (int)sizeof(AttnSmem));
    cudaFuncSetAttribute(gemm_mma_kernel<true>,
                         cudaFuncAttributeMaxDynamicSharedMemorySize, GEMM_SMEM_BYTES);
    cudaFuncSetAttribute(gemm_mma_kernel<false>,
                         cudaFuncAttributeMaxDynamicSharedMemorySize, GEMM_SMEM_BYTES);

    // 0) Producers: round once (numerically identical to consumer-side cvt)
    cvt_tf32_kernel<<<(ROWS * DIM / 4 + 255) / 256, 256>>>(x, xr, ROWS * DIM / 4);
    transpose_kernel<<<dim3(QKV_COLS / 32, DIM / 32), dim3(32, 8)>>>(
        w_qkv, wqkvT, DIM, QKV_COLS);
    transpose_kernel<<<dim3(DIM / 32, DIM / 32), dim3(32, 8)>>>(
        w_proj, wprojT, DIM, DIM);

    // 1) QKV projection (rounds output for attention)
    gemm_mma_kernel<true><<<dim3(QKV_COLS / 128, ROWS / 128), 256, GEMM_SMEM_BYTES>>>(
        xr, wqkvT, b_qkv, qkv, ROWS, QKV_COLS, DIM);

    // 2) Multi-head attention
    attn_kernel<<<dim3(SEQ / 128, BATCH * NHEAD), 256, sizeof(AttnSmem)>>>(qkv, att);

    // 3) Output projection (full fp32 output)
    gemm_mma_kernel<false><<<dim3(DIM / 128, ROWS / 128), 256, GEMM_SMEM_BYTES>>>(
        att, wprojT, b_proj, out, ROWS, DIM, DIM);
}

// round 10
// speedup vs baseline: 8.4384x; 1.7761x over previous
#include <cuda_runtime.h>
#include <cuda_fp16.h>
#include <math.h>
#include <stdint.h>

// Problem constants
#define BATCH 2
#define SEQ 2048
#define DIM 1024
#define NHEAD 16
#define HDIM 64
#define QKV_COLS (3 * DIM)          // 3072
#define ROWS (BATCH * SEQ)          // 4096
#define SCALE 0.03125f              // 1024^-0.5 (= 2^-5, exact)

// Scratch in device globals (no allocation allowed)
__device__ __half g_qkvh[ROWS * QKV_COLS];            // Q(pre-scaled),K as fp16
__device__ __half g_vT[BATCH * NHEAD * HDIM * SEQ];   // V transposed [bh][d][s]
__device__ __half g_atth[ROWS * DIM];                  // attention out, fp16
__device__ __half g_xh[ROWS * DIM];                    // x rounded to fp16
__device__ __half g_wqkvTh[QKV_COLS * DIM];            // [N][K] fp16
__device__ __half g_wprojTh[DIM * DIM];                // [N][K] fp16

// ---------------------------------------------------------------------------
// Helpers
// ---------------------------------------------------------------------------
// m16n8k16 fp16 MMA, fp32 accumulate.
// A frag: a0=A[g][2t4..+1], a1=A[g+8][2t4..+1], a2=A[g][2t4+8..+9], a3=A[g+8][+8..]
// B frag: b0=B[2t4..+1][g], b1=B[2t4+8..+9][g]
// C frag: c0,c1=C[g][2t4..+1], c2,c3=C[g+8][..]
__device__ __forceinline__ void mma_f16(float c[4],
    uint32_t a0, uint32_t a1, uint32_t a2, uint32_t a3,
    uint32_t b0, uint32_t b1)
{
    asm volatile(
        "mma.sync.aligned.m16n8k16.row.col.f32.f16.f16.f32 "
        "{%0,%1,%2,%3}, {%4,%5,%6,%7}, {%8,%9}, {%0,%1,%2,%3};"
        : "+f"(c[0]), "+f"(c[1]), "+f"(c[2]), "+f"(c[3])
        : "r"(a0), "r"(a1), "r"(a2), "r"(a3), "r"(b0), "r"(b1));
}

__device__ __forceinline__ uint32_t pack_h2(float lo, float hi) {
    __half2 h = __floats2half2_rn(lo, hi);
    return *reinterpret_cast<uint32_t*>(&h);
}

__device__ __forceinline__ uint32_t smem_u32(const void* p) {
    uint32_t a;
    asm("{ .reg .u64 t; cvta.to.shared.u64 t, %1; cvt.u32.u64 %0, t; }"
        : "=r"(a) : "l"(p));
    return a;
}

__device__ __forceinline__ void cp_async16(uint32_t dst, const void* src) {
    asm volatile("cp.async.cg.shared.global [%0], [%1], 16;"
                 :: "r"(dst), "l"(src));
}
#define CP_COMMIT() asm volatile("cp.async.commit_group;" ::: "memory")
#define CP_WAIT0()  asm volatile("cp.async.wait_group 0;" ::: "memory")

// k-slot permutation (QK^T and projection GEMMs): feed smem positions
// (4t4..4t4+3) into slots (2t4,2t4+1,2t4+8,2t4+9) on BOTH A and B sides —
// same bijection both sides => identical dot product, but each thread's four
// k-halfs are contiguous => one LDS.64 per fragment pair.

// ---------------------------------------------------------------------------
// x -> fp16
// ---------------------------------------------------------------------------
__global__ __launch_bounds__(256) void cvt_f16_kernel(
    const float* __restrict__ in, __half* __restrict__ out, int n4)
{
    const int i = blockIdx.x * 256 + threadIdx.x;
    if (i < n4) {
        float4 v = reinterpret_cast<const float4*>(in)[i];
        reinterpret_cast<__half2*>(out)[2 * i]     = __floats2half2_rn(v.x, v.y);
        reinterpret_cast<__half2*>(out)[2 * i + 1] = __floats2half2_rn(v.z, v.w);
    }
}

// ---------------------------------------------------------------------------
// Transpose + fp16 round: out[n*K + k] = fp16(in[k*N + n]).
// ---------------------------------------------------------------------------
__global__ __launch_bounds__(256) void transpose_kernel(
    const float* __restrict__ in, __half* __restrict__ out, int K, int N)
{
    __shared__ float tile[32][33];
    const int n0 = blockIdx.x * 32;
    const int k0 = blockIdx.y * 32;
    const int tx = threadIdx.x, ty = threadIdx.y;
#pragma unroll
    for (int i = 0; i < 32; i += 8)
        tile[ty + i][tx] = in[(size_t)(k0 + ty + i) * N + n0 + tx];
    __syncthreads();
#pragma unroll
    for (int i = 0; i < 32; i += 8)
        out[(size_t)(n0 + ty + i) * K + k0 + tx] =
            __float2half_rn(tile[tx][ty + i]);
}

// ---------------------------------------------------------------------------
// fp16 mma GEMM: C = A[M,K] @ Bt[N,K]^T + bias.
// 128x128 tile, BK=64 halfs (128B rows), cp.async double-buffered,
// 256 threads, 2 CTAs/SM, one barrier per chunk, LDS.64 fragments.
// MODE 0: plain fp32 output. MODE 1: QKV epilogue (Q scaled->qkvh, K->qkvh,
// V transposed -> vT), all fp16.
// ---------------------------------------------------------------------------
#define GSTRH 80                        // row stride halfs; word stride 40 == 8 mod 32
#define GSTGH (128 * GSTRH)             // halfs per tensor-stage
#define GEMM_SMEM_BYTES (4 * GSTGH * 2) // 81920 B

template <int MODE>
__global__ __launch_bounds__(256, 2) void gemm_f16_kernel(
    const __half* __restrict__ A, const __half* __restrict__ Bt,
    const float* __restrict__ bias, float* __restrict__ Cf,
    __half* __restrict__ qkvh, __half* __restrict__ vT,
    int M, int N, int K)
{
    extern __shared__ __half hsm[];
    __half* sA = hsm;
    __half* sB = hsm + 2 * GSTGH;
    const uint32_t sAb = smem_u32(sA);
    const uint32_t sBb = smem_u32(sB);

    const int t    = threadIdx.x;
    const int lane = t & 31;
    const int w    = t >> 5;
    const int wm   = w >> 2;
    const int wn   = w & 3;
    const int g    = lane >> 2;
    const int t4   = lane & 3;
    const int row0 = blockIdx.y * 128;
    const int col0 = blockIdx.x * 128;

    float acc[4][4][4];
#pragma unroll
    for (int i = 0; i < 4; i++)
#pragma unroll
        for (int j = 0; j < 4; j++)
#pragma unroll
            for (int q = 0; q < 4; q++) acc[i][j][q] = 0.0f;

    const int nchunk = K >> 6;   // BK = 64

    auto load_stage = [&](int stg, int ck) {
        const int k0 = ck << 6;
#pragma unroll
        for (int i = 0; i < 4; i++) {
            const int id = t + i * 256;     // 0..1023
            const int r  = id >> 3;         // 0..127
            const int c  = id & 7;          // 16B chunk (8 halfs)
            cp_async16(sAb + (uint32_t)((stg * GSTGH + r * GSTRH + c * 8) * 2),
                       A + (size_t)(row0 + r) * K + k0 + c * 8);
            cp_async16(sBb + (uint32_t)((stg * GSTGH + r * GSTRH + c * 8) * 2),
                       Bt + (size_t)(col0 + r) * K + k0 + c * 8);
        }
    };

    load_stage(0, 0);
    CP_COMMIT();

    for (int ck = 0; ck < nchunk; ck++) {
        CP_WAIT0();
        __syncthreads();
        if (ck + 1 < nchunk) {
            load_stage((ck + 1) & 1, ck + 1);
            CP_COMMIT();
        }

        const __half* cA = sA + (ck & 1) * GSTGH;
        const __half* cB = sB + (ck & 1) * GSTGH;

#pragma unroll
        for (int ks = 0; ks < 4; ks++) {
            const int koff = ks * 16 + 4 * t4;   // permuted positions
            uint2 alo[4], ahi[4];
#pragma unroll
            for (int mb = 0; mb < 4; mb++) {
                const int r = wm * 64 + mb * 16 + g;
                alo[mb] = *reinterpret_cast<const uint2*>(&cA[r * GSTRH + koff]);
                ahi[mb] = *reinterpret_cast<const uint2*>(&cA[(r + 8) * GSTRH + koff]);
            }
            uint2 bv[4];
#pragma unroll
            for (int nb = 0; nb < 4; nb++) {
                const int c = wn * 32 + nb * 8 + g;
                bv[nb] = *reinterpret_cast<const uint2*>(&cB[c * GSTRH + koff]);
            }
#pragma unroll
            for (int mb = 0; mb < 4; mb++)
#pragma unroll
                for (int nb = 0; nb < 4; nb++)
                    mma_f16(acc[mb][nb], alo[mb].x, ahi[mb].x, alo[mb].y,
                            ahi[mb].y, bv[nb].x, bv[nb].y);
        }
        // next iteration's top __syncthreads() orders reads before overwrite
    }

    // Epilogue
#pragma unroll
    for (int mb = 0; mb < 4; mb++) {
        const int r = row0 + wm * 64 + mb * 16 + g;
#pragma unroll
        for (int nb = 0; nb < 4; nb++) {
            const int c = col0 + wn * 32 + nb * 8 + 2 * t4;
            const float b0 = bias[c], b1 = bias[c + 1];
            const float v0 = acc[mb][nb][0] + b0, v1 = acc[mb][nb][1] + b1;
            const float v2 = acc[mb][nb][2] + b0, v3 = acc[mb][nb][3] + b1;
            if (MODE == 0) {
                *reinterpret_cast<float2*>(Cf + (size_t)r * N + c) =
                    make_float2(v0, v1);
                *reinterpret_cast<float2*>(Cf + (size_t)(r + 8) * N + c) =
                    make_float2(v2, v3);
            } else {
                const int h  = c / 192;
                const int cw = c - h * 192;
                if (cw < 128) {
                    const float s = (cw < 64) ? SCALE : 1.0f;
                    *reinterpret_cast<__half2*>(&qkvh[(size_t)r * QKV_COLS + c]) =
                        __floats2half2_rn(v0 * s, v1 * s);
                    *reinterpret_cast<__half2*>(&qkvh[(size_t)(r + 8) * QKV_COLS + c]) =
                        __floats2half2_rn(v2 * s, v3 * s);
                } else {
                    const int d  = cw - 128;
                    const int bb = r / SEQ;           // r, r+8 same batch
                    const int s_ = r - bb * SEQ;
                    __half* vr = vT + ((size_t)(bb * NHEAD + h) * HDIM + d) * SEQ;
                    vr[s_]           = __float2half_rn(v0);
                    vr[SEQ + s_]     = __float2half_rn(v1);
                    vr[s_ + 8]       = __float2half_rn(v2);
                    vr[SEQ + s_ + 8] = __float2half_rn(v3);
                }
            }
        }
    }
}

// ---------------------------------------------------------------------------
// Flash-attention v7 (fp16 mma): Q pre-scaled fp16 fragments in registers;
// K tile [key][dim] padded rows; V tile [dim][key] with XOR swizzle for
// conflict-free half2 loads; P stays in registers (sacc == PV A-fragment).
// cp.async double-buffered, 2 CTAs/SM, 8 warps x 16 q-rows. grid=(S/128, B*H).
// ---------------------------------------------------------------------------
#define KBSTR 80    // halfs; word stride 40 == 8 mod 32 -> conflict-free LDS.64

struct __align__(16) AttnSmem {
    __half   Kb[2][64 * KBSTR];   // 20480 B
    uint32_t Vt[2][2048];         // 64 dims x 32 words, swizzled; 16384 B
};

__global__ __launch_bounds__(256, 2) void attn_kernel(
    const __half* __restrict__ qkv, const __half* __restrict__ vTg,
    __half* __restrict__ outh)
{
    extern __shared__ char smem_raw[];
    AttnSmem& sm = *reinterpret_cast<AttnSmem*>(smem_raw);

    const int t    = threadIdx.x;
    const int lane = t & 31;
    const int w    = t >> 5;
    const int g    = lane >> 2;
    const int t4   = lane & 3;
    const int qr   = w * 16;

    const int qt = blockIdx.x;
    const int bh = blockIdx.y;          // b*16 + h
    const int b  = bh >> 4;
    const int h  = bh & 15;

    const int q0 = qt * 128;

    const uint32_t kb0 = smem_u32(&sm.Kb[0][0]);
    const uint32_t vt0 = smem_u32(&sm.Vt[0][0]);

    // K columns base in qkvh: [b*SEQ + s][h*192 + 64 + d]
    const __half* kg = qkv + (size_t)b * SEQ * QKV_COLS + h * 192 + 64;
    // V transposed rows: [bh*64 + d][s]
    const __half* vg = vTg + (size_t)bh * HDIM * SEQ;

    auto prefetch = [&](int kt, int bufi) {
#pragma unroll
        for (int i = 0; i < 2; i++) {
            const int id = t + i * 256;        // 0..511
            const int rr = id >> 3;            // key (K) or dim (V)
            const int cc = id & 7;             // 16B chunk
            // K tile: [key][dim], padded stride
            cp_async16(kb0 + (uint32_t)((bufi * 64 * KBSTR + rr * KBSTR + cc * 8) * 2),
                       kg + (size_t)(kt * 64 + rr) * QKV_COLS + cc * 8);
            // V tile: [dim][key], XOR-swizzled 16B chunks
            const uint32_t dw = (uint32_t)(bufi * 2048 + rr * 32 +
                                (((cc << 2) ^ ((rr & 7) << 2))));
            cp_async16(vt0 + dw * 4, vg + (size_t)rr * SEQ + kt * 64 + cc * 8);
        }
        CP_COMMIT();
    };

    // ---- Q fragments (pre-scaled fp16 in qkvh); permuted k-slots ----
    uint32_t Qf[4][4];
    {
        const __half* qlo = qkv + ((size_t)(b * SEQ + q0 + qr + g)) * QKV_COLS + h * 192;
        const __half* qhi = qlo + (size_t)8 * QKV_COLS;
#pragma unroll
        for (int ks = 0; ks < 4; ks++) {
            const int koff = ks * 16 + 4 * t4;
            const uint2 lo = *reinterpret_cast<const uint2*>(&qlo[koff]);
            const uint2 hi = *reinterpret_cast<const uint2*>(&qhi[koff]);
            Qf[ks][0] = lo.x; Qf[ks][1] = hi.x;
            Qf[ks][2] = lo.y; Qf[ks][3] = hi.y;
        }
    }

    float obuf[8][4];
#pragma unroll
    for (int nb = 0; nb < 8; nb++)
#pragma unroll
        for (int q = 0; q < 4; q++) obuf[nb][q] = 0.0f;

    float m_lo = -INFINITY, m_hi = -INFINITY;
    float l_lo = 0.0f, l_hi = 0.0f;

    prefetch(0, 0);

    const uint32_t X = (uint32_t)(g << 2);   // V swizzle per-thread constant

    const int NT = SEQ / 64;
    for (int kt = 0; kt < NT; kt++) {
        const int cur = kt & 1;
        CP_WAIT0();
        __syncthreads();
        if (kt + 1 < NT) prefetch(kt + 1, cur ^ 1);

        const __half*    KbC = &sm.Kb[cur][0];
        const uint32_t*  VtC = &sm.Vt[cur][0];

        // ---- S = Q @ K^T ----
        float sacc[8][4];
#pragma unroll
        for (int nb = 0; nb < 8; nb++)
#pragma unroll
            for (int q = 0; q < 4; q++) sacc[nb][q] = 0.0f;

#pragma unroll
        for (int ks = 0; ks < 4; ks++) {
            const int koff = ks * 16 + 4 * t4;
#pragma unroll
            for (int nb = 0; nb < 8; nb++) {
                const int kc = nb * 8 + g;
                const uint2 kv =
                    *reinterpret_cast<const uint2*>(&KbC[kc * KBSTR + koff]);
                mma_f16(sacc[nb], Qf[ks][0], Qf[ks][1], Qf[ks][2], Qf[ks][3],
                        kv.x, kv.y);
            }
        }

        // ---- warp-private online softmax (registers) ----
        float mx_lo = -INFINITY, mx_hi = -INFINITY;
#pragma unroll
        for (int nb = 0; nb < 8; nb++) {
            mx_lo = fmaxf(mx_lo, fmaxf(sacc[nb][0], sacc[nb][1]));
            mx_hi = fmaxf(mx_hi, fmaxf(sacc[nb][2], sacc[nb][3]));
        }
        mx_lo = fmaxf(mx_lo, __shfl_xor_sync(0xffffffffu, mx_lo, 1));
        mx_lo = fmaxf(mx_lo, __shfl_xor_sync(0xffffffffu, mx_lo, 2));
        mx_hi = fmaxf(mx_hi, __shfl_xor_sync(0xffffffffu, mx_hi, 1));
        mx_hi = fmaxf(mx_hi, __shfl_xor_sync(0xffffffffu, mx_hi, 2));

        const float mn_lo = fmaxf(m_lo, mx_lo);
        const float mn_hi = fmaxf(m_hi, mx_hi);
        const float alpha_lo = __expf(m_lo - mn_lo);
        const float alpha_hi = __expf(m_hi - mn_hi);
        m_lo = mn_lo; m_hi = mn_hi;

        float sum_lo = 0.0f, sum_hi = 0.0f;
#pragma unroll
        for (int nb = 0; nb < 8; nb++) {
            const float p0 = __expf(sacc[nb][0] - mn_lo);
            const float p1 = __expf(sacc[nb][1] - mn_lo);
            const float p2 = __expf(sacc[nb][2] - mn_hi);
            const float p3 = __expf(sacc[nb][3] - mn_hi);
            sum_lo += p0 + p1;
            sum_hi += p2 + p3;
            sacc[nb][0] = p0; sacc[nb][1] = p1;
            sacc[nb][2] = p2; sacc[nb][3] = p3;
        }
        sum_lo += __shfl_xor_sync(0xffffffffu, sum_lo, 1);
        sum_lo += __shfl_xor_sync(0xffffffffu, sum_lo, 2);
        sum_hi += __shfl_xor_sync(0xffffffffu, sum_hi, 1);
        sum_hi += __shfl_xor_sync(0xffffffffu, sum_hi, 2);
        l_lo = l_lo * alpha_lo + sum_lo;
        l_hi = l_hi * alpha_hi + sum_hi;

#pragma unroll
        for (int nb = 0; nb < 8; nb++) {
            obuf[nb][0] *= alpha_lo; obuf[nb][1] *= alpha_lo;
            obuf[nb][2] *= alpha_hi; obuf[nb][3] *= alpha_hi;
        }

        // ---- O += P @ V: A-fragments packed straight from sacc ----
        // block j covers keys 16j..16j+15: a0={P[g][16j+2t4,+1]} = sacc[2j][0,1]
        // a1 = sacc[2j][2,3] (row g+8), a2 = sacc[2j+1][0,1] (keys +8),
        // a3 = sacc[2j+1][2,3].
#pragma unroll
        for (int j = 0; j < 4; j++) {
            const uint32_t a0 = pack_h2(sacc[2 * j][0],     sacc[2 * j][1]);
            const uint32_t a1 = pack_h2(sacc[2 * j][2],     sacc[2 * j][3]);
            const uint32_t a2 = pack_h2(sacc[2 * j + 1][0], sacc[2 * j + 1][1]);
            const uint32_t a3 = pack_h2(sacc[2 * j + 1][2], sacc[2 * j + 1][3]);
#pragma unroll
            for (int nb = 0; nb < 8; nb++) {
                const int dc = nb * 8 + g;
                const uint32_t b0 = VtC[dc * 32 + (((8 * j + t4)     ^ X))];
                const uint32_t b1 = VtC[dc * 32 + (((8 * j + 4 + t4) ^ X))];
                mma_f16(obuf[nb], a0, a1, a2, a3, b0, b1);
            }
        }
    }

    // ---- epilogue: fp16 out (consumed by fp16 proj GEMM) ----
    const float inv_lo = 1.0f / l_lo;
    const float inv_hi = 1.0f / l_hi;
    __half* o_lo = outh + ((size_t)(b * SEQ + q0 + qr + g)) * DIM + h * HDIM;
    __half* o_hi = o_lo + (size_t)8 * DIM;
#pragma unroll
    for (int nb = 0; nb < 8; nb++) {
        const int c = nb * 8 + 2 * t4;
        *reinterpret_cast<__half2*>(&o_lo[c]) =
            __floats2half2_rn(obuf[nb][0] * inv_lo, obuf[nb][1] * inv_lo);
        *reinterpret_cast<__half2*>(&o_hi[c]) =
            __floats2half2_rn(obuf[nb][2] * inv_hi, obuf[nb][3] * inv_hi);
    }
}

// ---------------------------------------------------------------------------
extern "C" void kernel_launch(void* const* d_in, const int* in_sizes, int n_in,
                              void* d_out, int out_size)
{
    const float* x      = (const float*)d_in[0];
    const float* w_qkv  = (const float*)d_in[1];
    const float* b_qkv  = (const float*)d_in[2];
    const float* w_proj = (const float*)d_in[3];
    const float* b_proj = (const float*)d_in[4];
    float* out = (float*)d_out;

    __half *qkvh, *vT, *atth, *xh, *wqkvT, *wprojT;
    cudaGetSymbolAddress((void**)&qkvh, g_qkvh);
    cudaGetSymbolAddress((void**)&vT, g_vT);
    cudaGetSymbolAddress((void**)&atth, g_atth);
    cudaGetSymbolAddress((void**)&xh, g_xh);
    cudaGetSymbolAddress((void**)&wqkvT, g_wqkvTh);
    cudaGetSymbolAddress((void**)&wprojT, g_wprojTh);

    cudaFuncSetAttribute(attn_kernel, cudaFuncAttributeMaxDynamicSharedMemorySize,
                         (int)sizeof(AttnSmem));
    cudaFuncSetAttribute(gemm_f16_kernel<0>,
                         cudaFuncAttributeMaxDynamicSharedMemorySize, GEMM_SMEM_BYTES);
    cudaFuncSetAttribute(gemm_f16_kernel<1>,
                         cudaFuncAttributeMaxDynamicSharedMemorySize, GEMM_SMEM_BYTES);

    // 0) Producers: round to fp16 once
    cvt_f16_kernel<<<(ROWS * DIM / 4 + 255) / 256, 256>>>(x, xh, ROWS * DIM / 4);
    transpose_kernel<<<dim3(QKV_COLS / 32, DIM / 32), dim3(32, 8)>>>(
        w_qkv, wqkvT, DIM, QKV_COLS);
    transpose_kernel<<<dim3(DIM / 32, DIM / 32), dim3(32, 8)>>>(
        w_proj, wprojT, DIM, DIM);

    // 1) QKV projection (fp16 mma; epilogue scatters Q-scaled/K and V^T)
    gemm_f16_kernel<1><<<dim3(QKV_COLS / 128, ROWS / 128), 256, GEMM_SMEM_BYTES>>>(
        xh, wqkvT, b_qkv, nullptr, qkvh, vT, ROWS, QKV_COLS, DIM);

    // 2) Multi-head attention (fp16 mma)
    attn_kernel<<<dim3(SEQ / 128, BATCH * NHEAD), 256, sizeof(AttnSmem)>>>(
        qkvh, vT, atth);

    // 3) Output projection (fp16 mma, fp32 output)
    gemm_f16_kernel<0><<<dim3(DIM / 128, ROWS / 128), 256, GEMM_SMEM_BYTES>>>(
        atth, wprojT, b_proj, out, nullptr, nullptr, ROWS, DIM, DIM);
}

// round 11
// speedup vs baseline: 8.8674x; 1.0508x over previous
#include <cuda_runtime.h>
#include <cuda_fp16.h>
#include <math.h>
#include <stdint.h>

// Problem constants
#define BATCH 2
#define SEQ 2048
#define DIM 1024
#define NHEAD 16
#define HDIM 64
#define QKV_COLS (3 * DIM)          // 3072
#define ROWS (BATCH * SEQ)          // 4096
#define SCALE 0.03125f              // 1024^-0.5 (= 2^-5, exact)

// Scratch in device globals (no allocation allowed)
__device__ __half g_qkvh[ROWS * QKV_COLS];            // Q(pre-scaled),K as fp16
__device__ __half g_vT[BATCH * NHEAD * HDIM * SEQ];   // V transposed [bh][d][s]
__device__ __half g_atth[ROWS * DIM];                  // attention out, fp16
__device__ __half g_xh[ROWS * DIM];                    // x rounded to fp16
__device__ __half g_wqkvTh[QKV_COLS * DIM];            // [N][K] fp16
__device__ __half g_wprojTh[DIM * DIM];                // [1024,1024] fp16

// ---------------------------------------------------------------------------
// Helpers
// ---------------------------------------------------------------------------
// m16n8k16 fp16 MMA, fp32 accumulate (canonical fragment layouts).
__device__ __forceinline__ void mma_f16(float c[4],
    uint32_t a0, uint32_t a1, uint32_t a2, uint32_t a3,
    uint32_t b0, uint32_t b1)
{
    asm volatile(
        "mma.sync.aligned.m16n8k16.row.col.f32.f16.f16.f32 "
        "{%0,%1,%2,%3}, {%4,%5,%6,%7}, {%8,%9}, {%0,%1,%2,%3};"
        : "+f"(c[0]), "+f"(c[1]), "+f"(c[2]), "+f"(c[3])
        : "r"(a0), "r"(a1), "r"(a2), "r"(a3), "r"(b0), "r"(b1));
}

__device__ __forceinline__ void ldsm_x4(
    uint32_t& r0, uint32_t& r1, uint32_t& r2, uint32_t& r3, uint32_t addr)
{
    asm volatile(
        "ldmatrix.sync.aligned.m8n8.x4.shared.b16 {%0,%1,%2,%3}, [%4];"
        : "=r"(r0), "=r"(r1), "=r"(r2), "=r"(r3) : "r"(addr));
}

__device__ __forceinline__ uint32_t pack_h2(float lo, float hi) {
    __half2 h = __floats2half2_rn(lo, hi);
    return *reinterpret_cast<uint32_t*>(&h);
}

__device__ __forceinline__ uint32_t smem_u32(const void* p) {
    uint32_t a;
    asm("{ .reg .u64 t; cvta.to.shared.u64 t, %1; cvt.u32.u64 %0, t; }"
        : "=r"(a) : "l"(p));
    return a;
}

__device__ __forceinline__ void cp_async16(uint32_t dst, const void* src) {
    asm volatile("cp.async.cg.shared.global [%0], [%1], 16;"
                 :: "r"(dst), "l"(src));
}
#define CP_COMMIT() asm volatile("cp.async.commit_group;" ::: "memory")
#define CP_WAIT0()  asm volatile("cp.async.wait_group 0;" ::: "memory")

// ---------------------------------------------------------------------------
// x -> fp16
// ---------------------------------------------------------------------------
__global__ __launch_bounds__(256) void cvt_f16_kernel(
    const float* __restrict__ in, __half* __restrict__ out, int n4)
{
    const int i = blockIdx.x * 256 + threadIdx.x;
    if (i < n4) {
        float4 v = reinterpret_cast<const float4*>(in)[i];
        reinterpret_cast<__half2*>(out)[2 * i]     = __floats2half2_rn(v.x, v.y);
        reinterpret_cast<__half2*>(out)[2 * i + 1] = __floats2half2_rn(v.z, v.w);
    }
}

// ---------------------------------------------------------------------------
// Transpose + fp16 round: out[n*K + k] = fp16(in[k*N + n]).
// ---------------------------------------------------------------------------
__global__ __launch_bounds__(256) void transpose_kernel(
    const float* __restrict__ in, __half* __restrict__ out, int K, int N)
{
    __shared__ float tile[32][33];
    const int n0 = blockIdx.x * 32;
    const int k0 = blockIdx.y * 32;
    const int tx = threadIdx.x, ty = threadIdx.y;
#pragma unroll
    for (int i = 0; i < 32; i += 8)
        tile[ty + i][tx] = in[(size_t)(k0 + ty + i) * N + n0 + tx];
    __syncthreads();
#pragma unroll
    for (int i = 0; i < 32; i += 8)
        out[(size_t)(n0 + ty + i) * K + k0 + tx] =
            __float2half_rn(tile[tx][ty + i]);
}

// ---------------------------------------------------------------------------
// fp16 mma GEMM with ldmatrix fragments: C = A[M,K] @ Bt[N,K]^T + bias.
// 128x128 tile, BK=64 halfs, cp.async double-buffered, 256 threads,
// 2 CTAs/SM, one barrier per chunk. Row stride 72 halfs => conflict-free LDSM.
// MODE 0: fp32 output. MODE 1: QKV epilogue (Q scaled/K -> qkvh, V^T -> vT).
// ---------------------------------------------------------------------------
#define GSTRH 72                        // halfs per row (144 B)
#define GSTGH (128 * GSTRH)             // halfs per tensor-stage
#define GEMM_SMEM_BYTES (4 * GSTGH * 2) // 73728 B

template <int MODE>
__global__ __launch_bounds__(256, 2) void gemm_f16_kernel(
    const __half* __restrict__ A, const __half* __restrict__ Bt,
    const float* __restrict__ bias, float* __restrict__ Cf,
    __half* __restrict__ qkvh, __half* __restrict__ vT,
    int M, int N, int K)
{
    extern __shared__ __half hsm[];
    __half* sA = hsm;
    __half* sB = hsm + 2 * GSTGH;
    const uint32_t sAb = smem_u32(sA);
    const uint32_t sBb = smem_u32(sB);

    const int t    = threadIdx.x;
    const int lane = t & 31;
    const int w    = t >> 5;
    const int wm   = w >> 2;
    const int wn   = w & 3;
    const int g    = lane >> 2;
    const int t4   = lane & 3;
    const int row0 = blockIdx.y * 128;
    const int col0 = blockIdx.x * 128;

    // ldmatrix per-lane address components (bytes)
    // A x4: rows (lane>>3)&1 selects 8-row half, lanes&7 = row; lane>>4 = k-half
    const int arow = ((lane >> 3) & 1) * 8 + (lane & 7);
    const int acol = (lane >> 4) * 8;
    // B x4: lane>>4 selects n-block (8 cols), (lane>>3)&1 selects k-half
    const int brow = (lane >> 4) * 8 + (lane & 7);
    const int bk   = ((lane >> 3) & 1) * 8;

    uint32_t aoff[4], boff[2];
#pragma unroll
    for (int mb = 0; mb < 4; mb++)
        aoff[mb] = (uint32_t)(((wm * 64 + mb * 16 + arow) * GSTRH + acol) * 2);
#pragma unroll
    for (int nbp = 0; nbp < 2; nbp++)
        boff[nbp] = (uint32_t)(((wn * 32 + nbp * 16 + brow) * GSTRH + bk) * 2);

    float acc[4][4][4];
#pragma unroll
    for (int i = 0; i < 4; i++)
#pragma unroll
        for (int j = 0; j < 4; j++)
#pragma unroll
            for (int q = 0; q < 4; q++) acc[i][j][q] = 0.0f;

    const int nchunk = K >> 6;   // BK = 64

    auto load_stage = [&](int stg, int ck) {
        const int k0 = ck << 6;
#pragma unroll
        for (int i = 0; i < 4; i++) {
            const int id = t + i * 256;     // 0..1023
            const int r  = id >> 3;         // 0..127
            const int c  = id & 7;          // 16B chunk (8 halfs)
            cp_async16(sAb + (uint32_t)((stg * GSTGH + r * GSTRH) * 2 + c * 16),
                       A + (size_t)(row0 + r) * K + k0 + c * 8);
            cp_async16(sBb + (uint32_t)((stg * GSTGH + r * GSTRH) * 2 + c * 16),
                       Bt + (size_t)(col0 + r) * K + k0 + c * 8);
        }
    };

    load_stage(0, 0);
    CP_COMMIT();

    for (int ck = 0; ck < nchunk; ck++) {
        CP_WAIT0();
        __syncthreads();
        if (ck + 1 < nchunk) {
            load_stage((ck + 1) & 1, ck + 1);
            CP_COMMIT();
        }

        const uint32_t stA = sAb + (uint32_t)((ck & 1) * GSTGH * 2);
        const uint32_t stB = sBb + (uint32_t)((ck & 1) * GSTGH * 2);

#pragma unroll
        for (int ks = 0; ks < 4; ks++) {
            const uint32_t kso = (uint32_t)(ks * 32);   // 16 halfs
            uint32_t a[4][4];
#pragma unroll
            for (int mb = 0; mb < 4; mb++)
                ldsm_x4(a[mb][0], a[mb][1], a[mb][2], a[mb][3],
                        stA + aoff[mb] + kso);
            uint32_t bq[2][4];
#pragma unroll
            for (int nbp = 0; nbp < 2; nbp++)
                ldsm_x4(bq[nbp][0], bq[nbp][1], bq[nbp][2], bq[nbp][3],
                        stB + boff[nbp] + kso);
#pragma unroll
            for (int mb = 0; mb < 4; mb++) {
#pragma unroll
                for (int nbp = 0; nbp < 2; nbp++) {
                    mma_f16(acc[mb][2 * nbp],     a[mb][0], a[mb][1], a[mb][2],
                            a[mb][3], bq[nbp][0], bq[nbp][1]);
                    mma_f16(acc[mb][2 * nbp + 1], a[mb][0], a[mb][1], a[mb][2],
                            a[mb][3], bq[nbp][2], bq[nbp][3]);
                }
            }
        }
        // next iteration's top __syncthreads() orders reads before overwrite
    }

    // Epilogue
#pragma unroll
    for (int mb = 0; mb < 4; mb++) {
        const int r = row0 + wm * 64 + mb * 16 + g;
#pragma unroll
        for (int nb = 0; nb < 4; nb++) {
            const int c = col0 + wn * 32 + nb * 8 + 2 * t4;
            const float b0 = bias[c], b1 = bias[c + 1];
            const float v0 = acc[mb][nb][0] + b0, v1 = acc[mb][nb][1] + b1;
            const float v2 = acc[mb][nb][2] + b0, v3 = acc[mb][nb][3] + b1;
            if (MODE == 0) {
                *reinterpret_cast<float2*>(Cf + (size_t)r * N + c) =
                    make_float2(v0, v1);
                *reinterpret_cast<float2*>(Cf + (size_t)(r + 8) * N + c) =
                    make_float2(v2, v3);
            } else {
                const int h  = c / 192;
                const int cw = c - h * 192;
                if (cw < 128) {
                    const float s = (cw < 64) ? SCALE : 1.0f;
                    *reinterpret_cast<__half2*>(&qkvh[(size_t)r * QKV_COLS + c]) =
                        __floats2half2_rn(v0 * s, v1 * s);
                    *reinterpret_cast<__half2*>(&qkvh[(size_t)(r + 8) * QKV_COLS + c]) =
                        __floats2half2_rn(v2 * s, v3 * s);
                } else {
                    const int d  = cw - 128;
                    const int bb = r / SEQ;           // r, r+8 same batch
                    const int s_ = r - bb * SEQ;
                    __half* vr = vT + ((size_t)(bb * NHEAD + h) * HDIM + d) * SEQ;
                    vr[s_]           = __float2half_rn(v0);
                    vr[SEQ + s_]     = __float2half_rn(v1);
                    vr[s_ + 8]       = __float2half_rn(v2);
                    vr[SEQ + s_ + 8] = __float2half_rn(v3);
                }
            }
        }
    }
}

// ---------------------------------------------------------------------------
// Flash-attention v8 (fp16 mma + ldmatrix): Q fragments in registers; K tile
// [key][dim] and V tile [dim][key], both stride 72 halfs (conflict-free
// LDSM.x4). P stays in registers (sacc -> PV A-fragment pack). cp.async
// double-buffered, 2 CTAs/SM, 8 warps x 16 q-rows. grid = (S/128, B*H).
// ---------------------------------------------------------------------------
#define ASTR 72                         // halfs per row
#define ASTGH (64 * ASTR)               // halfs per tile-stage (9216 B)

struct __align__(16) AttnSmem {
    __half Kb[2][ASTGH];
    __half Vt[2][ASTGH];
};

__global__ __launch_bounds__(256, 2) void attn_kernel(
    const __half* __restrict__ qkv, const __half* __restrict__ vTg,
    __half* __restrict__ outh)
{
    extern __shared__ char smem_raw[];
    AttnSmem& sm = *reinterpret_cast<AttnSmem*>(smem_raw);

    const int t    = threadIdx.x;
    const int lane = t & 31;
    const int w    = t >> 5;
    const int g    = lane >> 2;
    const int t4   = lane & 3;
    const int qr   = w * 16;

    const int qt = blockIdx.x;
    const int bh = blockIdx.y;          // b*16 + h
    const int b  = bh >> 4;
    const int h  = bh & 15;

    const int q0 = qt * 128;

    const uint32_t kb0 = smem_u32(&sm.Kb[0][0]);
    const uint32_t vt0 = smem_u32(&sm.Vt[0][0]);

    // ldmatrix lane address components (B-style x4: lane>>4 = 8-row block,
    // (lane>>3)&1 = k-half)
    const int frow = (lane >> 4) * 8 + (lane & 7);
    const int fsel = ((lane >> 3) & 1) * 8;
    uint32_t foff[4];
#pragma unroll
    for (int nbp = 0; nbp < 4; nbp++)
        foff[nbp] = (uint32_t)(((nbp * 16 + frow) * ASTR + fsel) * 2);

    // K columns base in qkvh: [b*SEQ + s][h*192 + 64 + d]
    const __half* kg = qkv + (size_t)b * SEQ * QKV_COLS + h * 192 + 64;
    // V transposed rows: [bh*64 + d][s]
    const __half* vg = vTg + (size_t)bh * HDIM * SEQ;

    auto prefetch = [&](int kt, int bufi) {
        const uint32_t sb = (uint32_t)(bufi * ASTGH * 2);
#pragma unroll
        for (int i = 0; i < 2; i++) {
            const int id = t + i * 256;        // 0..511
            const int rr = id >> 3;            // key (K) or dim (V)
            const int cc = id & 7;             // 16B chunk
            cp_async16(kb0 + sb + (uint32_t)(rr * ASTR * 2 + cc * 16),
                       kg + (size_t)(kt * 64 + rr) * QKV_COLS + cc * 8);
            cp_async16(vt0 + sb + (uint32_t)(rr * ASTR * 2 + cc * 16),
                       vg + (size_t)rr * SEQ + kt * 64 + cc * 8);
        }
        CP_COMMIT();
    };

    // ---- Q fragments (pre-scaled fp16 in qkvh), canonical layout ----
    uint32_t Qf[4][4];
    {
        const __half* qlo = qkv + ((size_t)(b * SEQ + q0 + qr + g)) * QKV_COLS + h * 192;
        const __half* qhi = qlo + (size_t)8 * QKV_COLS;
#pragma unroll
        for (int ks = 0; ks < 4; ks++) {
            const int k0 = ks * 16 + 2 * t4;
            Qf[ks][0] = *reinterpret_cast<const uint32_t*>(&qlo[k0]);
            Qf[ks][1] = *reinterpret_cast<const uint32_t*>(&qhi[k0]);
            Qf[ks][2] = *reinterpret_cast<const uint32_t*>(&qlo[k0 + 8]);
            Qf[ks][3] = *reinterpret_cast<const uint32_t*>(&qhi[k0 + 8]);
        }
    }

    float obuf[8][4];
#pragma unroll
    for (int nb = 0; nb < 8; nb++)
#pragma unroll
        for (int q = 0; q < 4; q++) obuf[nb][q] = 0.0f;

    float m_lo = -INFINITY, m_hi = -INFINITY;
    float l_lo = 0.0f, l_hi = 0.0f;

    prefetch(0, 0);

    const int NT = SEQ / 64;
    for (int kt = 0; kt < NT; kt++) {
        const int cur = kt & 1;
        CP_WAIT0();
        __syncthreads();
        if (kt + 1 < NT) prefetch(kt + 1, cur ^ 1);

        const uint32_t stK = kb0 + (uint32_t)(cur * ASTGH * 2);
        const uint32_t stV = vt0 + (uint32_t)(cur * ASTGH * 2);

        // ---- S = Q @ K^T (ldmatrix K fragments) ----
        float sacc[8][4];
#pragma unroll
        for (int nb = 0; nb < 8; nb++)
#pragma unroll
            for (int q = 0; q < 4; q++) sacc[nb][q] = 0.0f;

#pragma unroll
        for (int ks = 0; ks < 4; ks++) {
            const uint32_t kso = (uint32_t)(ks * 32);
#pragma unroll
            for (int nbp = 0; nbp < 4; nbp++) {
                uint32_t k0_, k1_, k2_, k3_;
                ldsm_x4(k0_, k1_, k2_, k3_, stK + foff[nbp] + kso);
                mma_f16(sacc[2 * nbp],     Qf[ks][0], Qf[ks][1], Qf[ks][2],
                        Qf[ks][3], k0_, k1_);
                mma_f16(sacc[2 * nbp + 1], Qf[ks][0], Qf[ks][1], Qf[ks][2],
                        Qf[ks][3], k2_, k3_);
            }
        }

        // ---- warp-private online softmax (registers) ----
        float mx_lo = -INFINITY, mx_hi = -INFINITY;
#pragma unroll
        for (int nb = 0; nb < 8; nb++) {
            mx_lo = fmaxf(mx_lo, fmaxf(sacc[nb][0], sacc[nb][1]));
            mx_hi = fmaxf(mx_hi, fmaxf(sacc[nb][2], sacc[nb][3]));
        }
        mx_lo = fmaxf(mx_lo, __shfl_xor_sync(0xffffffffu, mx_lo, 1));
        mx_lo = fmaxf(mx_lo, __shfl_xor_sync(0xffffffffu, mx_lo, 2));
        mx_hi = fmaxf(mx_hi, __shfl_xor_sync(0xffffffffu, mx_hi, 1));
        mx_hi = fmaxf(mx_hi, __shfl_xor_sync(0xffffffffu, mx_hi, 2));

        const float mn_lo = fmaxf(m_lo, mx_lo);
        const float mn_hi = fmaxf(m_hi, mx_hi);
        const float alpha_lo = __expf(m_lo - mn_lo);
        const float alpha_hi = __expf(m_hi - mn_hi);
        m_lo = mn_lo; m_hi = mn_hi;

        float sum_lo = 0.0f, sum_hi = 0.0f;
#pragma unroll
        for (int nb = 0; nb < 8; nb++) {
            const float p0 = __expf(sacc[nb][0] - mn_lo);
            const float p1 = __expf(sacc[nb][1] - mn_lo);
            const float p2 = __expf(sacc[nb][2] - mn_hi);
            const float p3 = __expf(sacc[nb][3] - mn_hi);
            sum_lo += p0 + p1;
            sum_hi += p2 + p3;
            sacc[nb][0] = p0; sacc[nb][1] = p1;
            sacc[nb][2] = p2; sacc[nb][3] = p3;
        }
        sum_lo += __shfl_xor_sync(0xffffffffu, sum_lo, 1);
        sum_lo += __shfl_xor_sync(0xffffffffu, sum_lo, 2);
        sum_hi += __shfl_xor_sync(0xffffffffu, sum_hi, 1);
        sum_hi += __shfl_xor_sync(0xffffffffu, sum_hi, 2);
        l_lo = l_lo * alpha_lo + sum_lo;
        l_hi = l_hi * alpha_hi + sum_hi;

#pragma unroll
        for (int nb = 0; nb < 8; nb++) {
            obuf[nb][0] *= alpha_lo; obuf[nb][1] *= alpha_lo;
            obuf[nb][2] *= alpha_hi; obuf[nb][3] *= alpha_hi;
        }

        // ---- O += P @ V (A from sacc; V fragments via ldmatrix) ----
        // key block j (16 keys): a0 = {P[g][16j+2t4,+1]} = sacc[2j][0,1],
        // a1 = sacc[2j][2,3], a2 = sacc[2j+1][0,1], a3 = sacc[2j+1][2,3].
#pragma unroll
        for (int j = 0; j < 4; j++) {
            const uint32_t jso = (uint32_t)(j * 32);
            const uint32_t a0 = pack_h2(sacc[2 * j][0],     sacc[2 * j][1]);
            const uint32_t a1 = pack_h2(sacc[2 * j][2],     sacc[2 * j][3]);
            const uint32_t a2 = pack_h2(sacc[2 * j + 1][0], sacc[2 * j + 1][1]);
            const uint32_t a3 = pack_h2(sacc[2 * j + 1][2], sacc[2 * j + 1][3]);
#pragma unroll
            for (int nbp = 0; nbp < 4; nbp++) {
                uint32_t v0_, v1_, v2_, v3_;
                ldsm_x4(v0_, v1_, v2_, v3_, stV + foff[nbp] + jso);
                mma_f16(obuf[2 * nbp],     a0, a1, a2, a3, v0_, v1_);
                mma_f16(obuf[2 * nbp + 1], a0, a1, a2, a3, v2_, v3_);
            }
        }
    }

    // ---- epilogue: fp16 out (consumed by fp16 proj GEMM) ----
    const float inv_lo = 1.0f / l_lo;
    const float inv_hi = 1.0f / l_hi;
    __half* o_lo = outh + ((size_t)(b * SEQ + q0 + qr + g)) * DIM + h * HDIM;
    __half* o_hi = o_lo + (size_t)8 * DIM;
#pragma unroll
    for (int nb = 0; nb < 8; nb++) {
        const int c = nb * 8 + 2 * t4;
        *reinterpret_cast<__half2*>(&o_lo[c]) =
            __floats2half2_rn(obuf[nb][0] * inv_lo, obuf[nb][1] * inv_lo);
        *reinterpret_cast<__half2*>(&o_hi[c]) =
            __floats2half2_rn(obuf[nb][2] * inv_hi, obuf[nb][3] * inv_hi);
    }
}

// ---------------------------------------------------------------------------
extern "C" void kernel_launch(void* const* d_in, const int* in_sizes, int n_in,
                              void* d_out, int out_size)
{
    const float* x      = (const float*)d_in[0];
    const float* w_qkv  = (const float*)d_in[1];
    const float* b_qkv  = (const float*)d_in[2];
    const float* w_proj = (const float*)d_in[3];
    const float* b_proj = (const float*)d_in[4];
    float* out = (float*)d_out;

    __half *qkvh, *vT, *atth, *xh, *wqkvT, *wprojT;
    cudaGetSymbolAddress((void**)&qkvh, g_qkvh);
    cudaGetSymbolAddress((void**)&vT, g_vT);
    cudaGetSymbolAddress((void**)&atth, g_atth);
    cudaGetSymbolAddress((void**)&xh, g_xh);
    cudaGetSymbolAddress((void**)&wqkvT, g_wqkvTh);
    cudaGetSymbolAddress((void**)&wprojT, g_wprojTh);

    cudaFuncSetAttribute(attn_kernel, cudaFuncAttributeMaxDynamicSharedMemorySize,
                         (int)sizeof(AttnSmem));
    cudaFuncSetAttribute(gemm_f16_kernel<0>,
                         cudaFuncAttributeMaxDynamicSharedMemorySize, GEMM_SMEM_BYTES);
    cudaFuncSetAttribute(gemm_f16_kernel<1>,
                         cudaFuncAttributeMaxDynamicSharedMemorySize, GEMM_SMEM_BYTES);

    // 0) Producers: round to fp16 once
    cvt_f16_kernel<<<(ROWS * DIM / 4 + 255) / 256, 256>>>(x, xh, ROWS * DIM / 4);
    transpose_kernel<<<dim3(QKV_COLS / 32, DIM / 32), dim3(32, 8)>>>(
        w_qkv, wqkvT, DIM, QKV_COLS);
    transpose_kernel<<<dim3(DIM / 32, DIM / 32), dim3(32, 8)>>>(
        w_proj, wprojT, DIM, DIM);

    // 1) QKV projection (fp16 mma; epilogue scatters Q-scaled/K and V^T)
    gemm_f16_kernel<1><<<dim3(QKV_COLS / 128, ROWS / 128), 256, GEMM_SMEM_BYTES>>>(
        xh, wqkvT, b_qkv, nullptr, qkvh, vT, ROWS, QKV_COLS, DIM);

    // 2) Multi-head attention (fp16 mma + ldmatrix)
    attn_kernel<<<dim3(SEQ / 128, BATCH * NHEAD), 256, sizeof(AttnSmem)>>>(
        qkvh, vT, atth);

    // 3) Output projection (fp16 mma, fp32 output)
    gemm_f16_kernel<0><<<dim3(DIM / 128, ROWS / 128), 256, GEMM_SMEM_BYTES>>>(
        atth, wprojT, b_proj, out, nullptr, nullptr, ROWS, DIM, DIM);
}